// round 10
// baseline (speedup 1.0000x reference)
#include <cuda_runtime.h>
#include <cstdint>
#include <math.h>

#define BATCH   2
#define SEQLEN  2048
#define DMODEL  1024
#define NHEADS  16
#define DHEAD   64
#define FFDIM   4096
#define BL      (BATCH*SEQLEN)          // 4096
#define NPER    (SEQLEN*DMODEL)        // per-batch layernorm size

// ---------------- scratch (static device globals; no allocation allowed) ----
__device__ float g_xr  [BL*DMODEL];     // tf32-rounded x (GEMM A operand)
__device__ float g_q   [BL*DMODEL];
__device__ float g_k   [BL*DMODEL];
__device__ float g_v   [BL*DMODEL];
__device__ float g_attn[BL*DMODEL];
__device__ float g_h   [BL*DMODEL];
__device__ float g_hr  [BL*DMODEL];     // tf32-rounded h (FF1 A operand)
__device__ float g_ff1 [BL*FFDIM];
__device__ float g_ff2 [BL*DMODEL];
__device__ double g_part[BATCH*256*2];
__device__ float  g_stats[BATCH*2];

// --------------------------------------------------------- tf32 helpers ----
__device__ __forceinline__ uint32_t f2tf32(float x) {
    uint32_t u;
    asm("cvt.rna.tf32.f32 %0, %1;" : "=r"(u) : "f"(x));
    return u;
}

__device__ __forceinline__ void mma_tf32(float* c, const uint32_t* a, const uint32_t* b) {
    asm volatile(
        "mma.sync.aligned.m16n8k8.row.col.f32.tf32.tf32.f32 "
        "{%0,%1,%2,%3}, {%4,%5,%6,%7}, {%8,%9}, {%0,%1,%2,%3};"
        : "+f"(c[0]), "+f"(c[1]), "+f"(c[2]), "+f"(c[3])
        : "r"(a[0]), "r"(a[1]), "r"(a[2]), "r"(a[3]), "r"(b[0]), "r"(b[1]));
}

__device__ __forceinline__ void cp_async16(uint32_t saddr, const void* gptr) {
    asm volatile("cp.async.ca.shared.global [%0], [%1], 16;" :: "r"(saddr), "l"(gptr));
}
__device__ __forceinline__ void cp_async_commit() {
    asm volatile("cp.async.commit_group;");
}
__device__ __forceinline__ void cp_async_wait0() {
    asm volatile("cp.async.wait_group 0;");
}

// software 2^t on FMA/ALU pipes (avoids MUFU bottleneck). t <= 0 expected.
__device__ __forceinline__ float exp2s(float t) {
    t = fmaxf(t, -126.0f);
    float z = t + 12582912.0f;                    // round-to-int magic (1.5*2^23)
    int ni = __float_as_int(z) - 0x4B400000;
    float f = t - (z - 12582912.0f);              // f in [-0.5, 0.5]
    float p = 1.3333558e-3f;
    p = fmaf(p, f, 9.6181291e-3f);
    p = fmaf(p, f, 5.5504109e-2f);
    p = fmaf(p, f, 2.4022651e-1f);
    p = fmaf(p, f, 6.9314718e-1f);
    p = fmaf(p, f, 1.0f);
    return p * __int_as_float((ni + 127) << 23);
}

// -------------------------------------------------- tf32 GEMM (B from L2) ---
// C[M,N] = A[M,K] @ W[K,N] + bias (+relu, +round). A is PRE-ROUNDED to tf32,
// staged via cp.async into smem (raw bits are valid tf32). W (raw fp32) is
// loaded fragment-direct from gmem/L2, cvt.rna in registers, double-buffered
// one chunk ahead. This removes the B tile from the smem crossbar (64KB ->
// 40KB per chunk), which is the measured bottleneck.
#define TBM 128
#define TBN 128
#define TBK 16
#define ASTRIDE 20     // A smem [m][k] stride: (20*q + r) mod 32 covers all banks

__device__ __forceinline__ void gemm_bl_body(
    const float* __restrict__ A, const float* __restrict__ W,
    const float* __restrict__ bias, float* __restrict__ C,
    int M, int N, int K, int relu, int rnd,
    int bx, int by, uint32_t* As /* [2][TBM*ASTRIDE] */)
{
    const int tid  = threadIdx.x;
    const int lane = tid & 31;
    const int warp = tid >> 5;
    const int q = lane >> 2, r = lane & 3;
    const int wr = warp >> 2, wc = warp & 3;
    const int bm = by * TBM, bn = bx * TBN;

    // A loader mapping: rows arow, arow+64; k cols akc..akc+3
    const int arow = tid >> 2;
    const int akc  = (tid & 3) * 4;
    const float* Ag = A + (size_t)(bm + arow) * K + akc;

    uint32_t sA[2][2];
    sA[0][0] = (uint32_t)__cvta_generic_to_shared(&As[arow*ASTRIDE + akc]);
    sA[0][1] = (uint32_t)__cvta_generic_to_shared(&As[(arow + 64)*ASTRIDE + akc]);
    sA[1][0] = sA[0][0] + TBM*ASTRIDE*4;
    sA[1][1] = sA[0][1] + TBM*ASTRIDE*4;

    // B fragment-direct base: element (k = r + s*8 + 4e, n = bn + wc*32 + nf*8 + q)
    const float* Wg = W + (size_t)r * N + bn + wc*32 + q;

    float acc[4][4][4];
    #pragma unroll
    for (int i = 0; i < 4; i++)
        #pragma unroll
        for (int j = 0; j < 4; j++)
            #pragma unroll
            for (int e = 0; e < 4; e++) acc[i][j][e] = 0.f;

    float bstage[16];

    // prologue: chunk 0
    cp_async16(sA[0][0], Ag);
    cp_async16(sA[0][1], Ag + (size_t)64 * K);
    cp_async_commit();
    Ag += TBK;
    #pragma unroll
    for (int s = 0; s < 2; s++)
        #pragma unroll
        for (int e = 0; e < 2; e++)
            #pragma unroll
            for (int nf = 0; nf < 4; nf++)
                bstage[(s*2+e)*4 + nf] = __ldg(Wg + (size_t)(s*8 + 4*e)*N + nf*8);
    Wg += (size_t)TBK * N;
    cp_async_wait0();
    __syncthreads();

    const int nchunk = K / TBK;
    #pragma unroll 1
    for (int c = 0; c < nchunk; c++) {
        const int cur = c & 1;
        const bool has_next = (c + 1 < nchunk);

        // convert staged B to tf32 for this chunk
        uint32_t bf[2][4][2];
        #pragma unroll
        for (int s = 0; s < 2; s++)
            #pragma unroll
            for (int e = 0; e < 2; e++)
                #pragma unroll
                for (int nf = 0; nf < 4; nf++)
                    bf[s][nf][e] = f2tf32(bstage[(s*2+e)*4 + nf]);

        // prefetch next chunk (A -> smem buf^1, B -> bstage regs)
        if (has_next) {
            cp_async16(sA[cur^1][0], Ag);
            cp_async16(sA[cur^1][1], Ag + (size_t)64 * K);
            cp_async_commit();
            Ag += TBK;
            #pragma unroll
            for (int s = 0; s < 2; s++)
                #pragma unroll
                for (int e = 0; e < 2; e++)
                    #pragma unroll
                    for (int nf = 0; nf < 4; nf++)
                        bstage[(s*2+e)*4 + nf] = __ldg(Wg + (size_t)(s*8 + 4*e)*N + nf*8);
            Wg += (size_t)TBK * N;
        }

        // compute: 2 k8 steps x 4 m-tiles x 4 n-frags
        const uint32_t* Ab = As + cur * (TBM*ASTRIDE);
        #pragma unroll
        for (int k8 = 0; k8 < TBK; k8 += 8) {
            #pragma unroll
            for (int tm = 0; tm < 4; tm++) {
                const int m = wr*64 + tm*16 + q;
                uint32_t af[4];
                af[0] = Ab[m*ASTRIDE + k8 + r];
                af[1] = Ab[(m + 8)*ASTRIDE + k8 + r];
                af[2] = Ab[m*ASTRIDE + k8 + r + 4];
                af[3] = Ab[(m + 8)*ASTRIDE + k8 + r + 4];
                #pragma unroll
                for (int tn = 0; tn < 4; tn++)
                    mma_tf32(acc[tm][tn], af, bf[k8 >> 3][tn]);
            }
        }

        if (has_next) {
            cp_async_wait0();
            __syncthreads();
        }
    }

    // epilogue: bias (+relu) (+tf32 round), fragment layout -> global
    #pragma unroll
    for (int tm = 0; tm < 4; tm++) {
        const int row = bm + wr*64 + tm*16 + q;
        #pragma unroll
        for (int tn = 0; tn < 4; tn++) {
            const int col = bn + wc*32 + tn*8 + 2*r;
            const float2 bv = *(const float2*)(bias + col);
            float c0 = acc[tm][tn][0] + bv.x, c1 = acc[tm][tn][1] + bv.y;
            float c2 = acc[tm][tn][2] + bv.x, c3 = acc[tm][tn][3] + bv.y;
            if (relu) {
                c0 = fmaxf(c0, 0.f); c1 = fmaxf(c1, 0.f);
                c2 = fmaxf(c2, 0.f); c3 = fmaxf(c3, 0.f);
            }
            if (rnd) {
                c0 = __uint_as_float(f2tf32(c0)); c1 = __uint_as_float(f2tf32(c1));
                c2 = __uint_as_float(f2tf32(c2)); c3 = __uint_as_float(f2tf32(c3));
            }
            *(float2*)(C + (size_t)row*N + col)       = make_float2(c0, c1);
            *(float2*)(C + (size_t)(row + 8)*N + col) = make_float2(c2, c3);
        }
    }
}

__global__ __launch_bounds__(256) void tf32_gemm_bl(
    const float* __restrict__ A, const float* __restrict__ W,
    const float* __restrict__ bias, float* __restrict__ C,
    int M, int N, int K, int relu, int rnd)
{
    __shared__ uint32_t As[2*TBM*ASTRIDE];
    gemm_bl_body(A, W, bias, C, M, N, K, relu, rnd, blockIdx.x, blockIdx.y, As);
}

// fused QKV: blockIdx.z selects projection (saves launches, packs waves)
__global__ __launch_bounds__(256) void qkv_gemm_bl(
    const float* __restrict__ A,
    const float* __restrict__ wq, const float* __restrict__ bq, float* __restrict__ q,
    const float* __restrict__ wk, const float* __restrict__ bk, float* __restrict__ k,
    const float* __restrict__ wv, const float* __restrict__ bv, float* __restrict__ v)
{
    __shared__ uint32_t As[2*TBM*ASTRIDE];
    const int z = blockIdx.z;
    const float* W    = (z == 0) ? wq : (z == 1) ? wk : wv;
    const float* bias = (z == 0) ? bq : (z == 1) ? bk : bv;
    float*       C    = (z == 0) ? q  : (z == 1) ? k  : v;
    gemm_bl_body(A, W, bias, C, BL, DMODEL, DMODEL, 0, 1, blockIdx.x, blockIdx.y, As);
}

// elementwise tf32 rounding pass (for the external input x)
__global__ __launch_bounds__(256) void round_tf32_pass(
    const float* __restrict__ in, float* __restrict__ out)
{
    size_t i = ((size_t)blockIdx.x * blockDim.x + threadIdx.x) * 4;
    float4 vv = *(const float4*)(in + i);
    uint4 o = make_uint4(f2tf32(vv.x), f2tf32(vv.y), f2tf32(vv.z), f2tf32(vv.w));
    *(uint4*)(out + i) = o;
}

// --------------------------------------- tensor-core flash attention -------
#define FA_BR 128
#define FA_BC 32
#define PS_STRIDE 36
#define KS_STRIDE 40
#define VS_STRIDE 72

__global__ __launch_bounds__(256) void flash_attn_tc(
    const float* __restrict__ Q, const float* __restrict__ K,
    const float* __restrict__ V, float* __restrict__ O)
{
    __shared__ uint32_t KsT[64*KS_STRIDE];
    __shared__ uint32_t Vs [FA_BC*VS_STRIDE];
    __shared__ uint32_t Ps [FA_BR*PS_STRIDE];

    const int tid  = threadIdx.x;
    const int lane = tid & 31;
    const int warp = tid >> 5;
    const int qg = lane >> 2, r = lane & 3;
    const int b = blockIdx.z, h = blockIdx.y;
    const int q0 = blockIdx.x * FA_BR;
    const size_t base = ((size_t)b * SEQLEN) * DMODEL + h * DHEAD;

    const int mrow = warp*16 + qg;

    uint32_t qf[8][4];
    {
        const float* qp  = Q + base + (size_t)(q0 + mrow) * DMODEL;
        const float* qp8 = qp + (size_t)8 * DMODEL;
        #pragma unroll
        for (int ks = 0; ks < 8; ks++) {
            qf[ks][0] = f2tf32(__ldg(qp  + ks*8 + r));
            qf[ks][1] = f2tf32(__ldg(qp8 + ks*8 + r));
            qf[ks][2] = f2tf32(__ldg(qp  + ks*8 + r + 4));
            qf[ks][3] = f2tf32(__ldg(qp8 + ks*8 + r + 4));
        }
    }

    float oc[8][4];
    #pragma unroll
    for (int nf = 0; nf < 8; nf++)
        #pragma unroll
        for (int e = 0; e < 4; e++) oc[nf][e] = 0.f;
    float m0 = -INFINITY, m1 = -INFINITY, l0 = 0.f, l1 = 0.f;

    const int vrow = tid >> 3;
    const int vc0  = (tid & 7) * 4;

    const float SCL = 0.125f * 1.44269504f;

    for (int kt = 0; kt < SEQLEN/FA_BC; kt++) {
        __syncthreads();
        {
            const float* kp = K + base + (size_t)(kt*FA_BC + lane)*DMODEL + warp*8;
            float4 k0 = *(const float4*)kp;
            float4 k1 = *(const float4*)(kp + 4);
            KsT[(warp*8+0)*KS_STRIDE + lane] = f2tf32(k0.x);
            KsT[(warp*8+1)*KS_STRIDE + lane] = f2tf32(k0.y);
            KsT[(warp*8+2)*KS_STRIDE + lane] = f2tf32(k0.z);
            KsT[(warp*8+3)*KS_STRIDE + lane] = f2tf32(k0.w);
            KsT[(warp*8+4)*KS_STRIDE + lane] = f2tf32(k1.x);
            KsT[(warp*8+5)*KS_STRIDE + lane] = f2tf32(k1.y);
            KsT[(warp*8+6)*KS_STRIDE + lane] = f2tf32(k1.z);
            KsT[(warp*8+7)*KS_STRIDE + lane] = f2tf32(k1.w);
            const float* vp = V + base + (size_t)(kt*FA_BC + vrow)*DMODEL + vc0;
            float4 v0 = *(const float4*)vp;
            float4 v1 = *(const float4*)(vp + 32);
            *(uint4*)&Vs[vrow*VS_STRIDE + vc0] =
                make_uint4(f2tf32(v0.x), f2tf32(v0.y), f2tf32(v0.z), f2tf32(v0.w));
            *(uint4*)&Vs[vrow*VS_STRIDE + vc0 + 32] =
                make_uint4(f2tf32(v1.x), f2tf32(v1.y), f2tf32(v1.z), f2tf32(v1.w));
        }
        __syncthreads();

        float sc[4][4];
        #pragma unroll
        for (int nf = 0; nf < 4; nf++)
            #pragma unroll
            for (int e = 0; e < 4; e++) sc[nf][e] = 0.f;

        #pragma unroll
        for (int ks = 0; ks < 8; ks++) {
            uint32_t bfr[4][2];
            #pragma unroll
            for (int nf = 0; nf < 4; nf++) {
                bfr[nf][0] = KsT[(ks*8 + r)*KS_STRIDE + nf*8 + qg];
                bfr[nf][1] = KsT[(ks*8 + r + 4)*KS_STRIDE + nf*8 + qg];
            }
            #pragma unroll
            for (int nf = 0; nf < 4; nf++)
                mma_tf32(sc[nf], qf[ks], bfr[nf]);
        }

        float rm0 = -INFINITY, rm1 = -INFINITY;
        #pragma unroll
        for (int nf = 0; nf < 4; nf++) {
            rm0 = fmaxf(rm0, fmaxf(sc[nf][0], sc[nf][1]));
            rm1 = fmaxf(rm1, fmaxf(sc[nf][2], sc[nf][3]));
        }
        rm0 = fmaxf(rm0, __shfl_xor_sync(0xffffffffu, rm0, 1));
        rm0 = fmaxf(rm0, __shfl_xor_sync(0xffffffffu, rm0, 2));
        rm1 = fmaxf(rm1, __shfl_xor_sync(0xffffffffu, rm1, 1));
        rm1 = fmaxf(rm1, __shfl_xor_sync(0xffffffffu, rm1, 2));

        const float mt0 = fmaxf(m0, rm0 * SCL);
        const float mt1 = fmaxf(m1, rm1 * SCL);
        const float c0 = exp2s(m0 - mt0);
        const float c1 = exp2s(m1 - mt1);
        m0 = mt0; m1 = mt1;

        float rs0 = 0.f, rs1 = 0.f;
        #pragma unroll
        for (int nf = 0; nf < 4; nf++) {
            const float p0 = exp2s(fmaf(sc[nf][0], SCL, -mt0));
            const float p1 = exp2s(fmaf(sc[nf][1], SCL, -mt0));
            const float p2 = exp2s(fmaf(sc[nf][2], SCL, -mt1));
            const float p3 = exp2s(fmaf(sc[nf][3], SCL, -mt1));
            rs0 += p0 + p1;
            rs1 += p2 + p3;
            const int colw = nf*8 + 2*r;
            *(uint2*)&Ps[(mrow)*PS_STRIDE + colw]     = make_uint2(f2tf32(p0), f2tf32(p1));
            *(uint2*)&Ps[(mrow + 8)*PS_STRIDE + colw] = make_uint2(f2tf32(p2), f2tf32(p3));
        }
        rs0 += __shfl_xor_sync(0xffffffffu, rs0, 1);
        rs0 += __shfl_xor_sync(0xffffffffu, rs0, 2);
        rs1 += __shfl_xor_sync(0xffffffffu, rs1, 1);
        rs1 += __shfl_xor_sync(0xffffffffu, rs1, 2);
        l0 = l0*c0 + rs0;
        l1 = l1*c1 + rs1;

        #pragma unroll
        for (int nf = 0; nf < 8; nf++) {
            oc[nf][0] *= c0; oc[nf][1] *= c0;
            oc[nf][2] *= c1; oc[nf][3] *= c1;
        }
        __syncwarp();

        #pragma unroll
        for (int ks = 0; ks < 4; ks++) {
            uint32_t af[4];
            af[0] = Ps[(mrow)*PS_STRIDE     + ks*8 + r];
            af[1] = Ps[(mrow + 8)*PS_STRIDE + ks*8 + r];
            af[2] = Ps[(mrow)*PS_STRIDE     + ks*8 + r + 4];
            af[3] = Ps[(mrow + 8)*PS_STRIDE + ks*8 + r + 4];
            #pragma unroll
            for (int nf = 0; nf < 8; nf++) {
                uint32_t bf2[2];
                bf2[0] = Vs[(ks*8 + r)*VS_STRIDE + nf*8 + qg];
                bf2[1] = Vs[(ks*8 + r + 4)*VS_STRIDE + nf*8 + qg];
                mma_tf32(oc[nf], af, bf2);
            }
        }
    }

    const float inv0 = 1.0f / l0;
    const float inv1 = 1.0f / l1;
    float* op  = O + base + (size_t)(q0 + mrow) * DMODEL;
    float* op8 = op + (size_t)8 * DMODEL;
    #pragma unroll
    for (int nf = 0; nf < 8; nf++) {
        const int col = nf*8 + 2*r;
        *(float2*)(op  + col) = make_float2(oc[nf][0]*inv0, oc[nf][1]*inv0);
        *(float2*)(op8 + col) = make_float2(oc[nf][2]*inv1, oc[nf][3]*inv1);
    }
}

// ------------------------------------------------------------ layernorm ----
__global__ __launch_bounds__(256) void ln_reduce(
    const float* __restrict__ a, const float* __restrict__ b,
    double* __restrict__ part)
{
    const int batch = blockIdx.y;
    const float* pa = a + (size_t)batch * NPER;
    const float* pb = b + (size_t)batch * NPER;
    double s = 0.0, ss = 0.0;
    for (int i = blockIdx.x*blockDim.x + threadIdx.x; i < NPER;
         i += gridDim.x*blockDim.x) {
        float z = pa[i] + pb[i];
        s += (double)z;
        ss += (double)z * (double)z;
    }
    __shared__ double sh[512];
    int tid = threadIdx.x;
    sh[tid] = s; sh[256 + tid] = ss;
    __syncthreads();
    for (int st = 128; st > 0; st >>= 1) {
        if (tid < st) { sh[tid] += sh[tid+st]; sh[256+tid] += sh[256+tid+st]; }
        __syncthreads();
    }
    if (tid == 0) {
        part[(batch*256 + blockIdx.x)*2 + 0] = sh[0];
        part[(batch*256 + blockIdx.x)*2 + 1] = sh[256];
    }
}

__global__ __launch_bounds__(256) void ln_stats(
    const double* __restrict__ part, float* __restrict__ stats)
{
    const int batch = blockIdx.x;
    int tid = threadIdx.x;
    __shared__ double sh[512];
    sh[tid]       = part[(batch*256 + tid)*2 + 0];
    sh[256 + tid] = part[(batch*256 + tid)*2 + 1];
    __syncthreads();
    for (int st = 128; st > 0; st >>= 1) {
        if (tid < st) { sh[tid] += sh[tid+st]; sh[256+tid] += sh[256+tid+st]; }
        __syncthreads();
    }
    if (tid == 0) {
        double mean = sh[0] / (double)NPER;
        double var  = sh[256] / (double)NPER - mean*mean + 1e-5;
        stats[batch*2 + 0] = (float)mean;
        stats[batch*2 + 1] = (float)(1.0 / sqrt(var));
    }
}

// writes full-precision `out`; optionally also tf32-rounded `out_r`
__global__ __launch_bounds__(256) void ln_apply(
    const float* __restrict__ a, const float* __restrict__ b,
    const float* __restrict__ stats, float* __restrict__ out,
    float* __restrict__ out_r)
{
    const int batch = blockIdx.y;
    const float mean = stats[batch*2 + 0];
    const float inv  = stats[batch*2 + 1];
    size_t off = (size_t)batch * NPER + (size_t)(blockIdx.x*blockDim.x + threadIdx.x)*4;
    float4 va = *(const float4*)(a + off);
    float4 vb = *(const float4*)(b + off);
    float4 o;
    o.x = (va.x + vb.x - mean) * inv;
    o.y = (va.y + vb.y - mean) * inv;
    o.z = (va.z + vb.z - mean) * inv;
    o.w = (va.w + vb.w - mean) * inv;
    *(float4*)(out + off) = o;
    if (out_r) {
        uint4 orr = make_uint4(f2tf32(o.x), f2tf32(o.y), f2tf32(o.z), f2tf32(o.w));
        *(uint4*)(out_r + off) = orr;
    }
}

// -------------------------------------------------------------- launch -----
extern "C" void kernel_launch(void* const* d_in, const int* in_sizes, int n_in,
                              void* d_out, int out_size)
{
    const float* x  = (const float*)d_in[0];
    const float* wq = (const float*)d_in[1];
    const float* bq = (const float*)d_in[2];
    const float* wk = (const float*)d_in[3];
    const float* bk = (const float*)d_in[4];
    const float* wv = (const float*)d_in[5];
    const float* bv = (const float*)d_in[6];
    const float* w1 = (const float*)d_in[7];
    const float* b1 = (const float*)d_in[8];
    const float* w2 = (const float*)d_in[9];
    const float* b2 = (const float*)d_in[10];
    float* out = (float*)d_out;

    float *xr, *q, *k, *v, *attn, *h, *hr, *ff1, *ff2, *stats;
    double* part;
    cudaGetSymbolAddress((void**)&xr,   g_xr);
    cudaGetSymbolAddress((void**)&q,    g_q);
    cudaGetSymbolAddress((void**)&k,    g_k);
    cudaGetSymbolAddress((void**)&v,    g_v);
    cudaGetSymbolAddress((void**)&attn, g_attn);
    cudaGetSymbolAddress((void**)&h,    g_h);
    cudaGetSymbolAddress((void**)&hr,   g_hr);
    cudaGetSymbolAddress((void**)&ff1,  g_ff1);
    cudaGetSymbolAddress((void**)&ff2,  g_ff2);
    cudaGetSymbolAddress((void**)&part, g_part);
    cudaGetSymbolAddress((void**)&stats, g_stats);

    // round external input x -> xr (GEMM A operand must be pre-rounded)
    round_tf32_pass<<<(BL*DMODEL)/1024, 256>>>(x, xr);

    // fused QKV projections (tensor cores, tf32; outputs rounded)
    qkv_gemm_bl<<<dim3(DMODEL/TBN, BL/TBM, 3), 256>>>(
        xr, wq, bq, q, wk, bk, k, wv, bv, v);

    // attention (tensor cores + software exp2)
    flash_attn_tc<<<dim3(SEQLEN/FA_BR, NHEADS, BATCH), 256>>>(q, k, v, attn);

    // residual + LN1 -> h (full) and hr (rounded, FF1 A operand)
    ln_reduce<<<dim3(256, BATCH), 256>>>(x, attn, part);
    ln_stats <<<BATCH, 256>>>(part, stats);
    ln_apply <<<dim3(NPER/1024, BATCH), 256>>>(x, attn, stats, h, hr);

    // FFN (tensor cores, tf32). FF1 output rounded (feeds FF2 A), FF2 full.
    tf32_gemm_bl<<<dim3(FFDIM/TBN,  BL/TBM), 256>>>(hr,  w1, b1, ff1, BL, FFDIM,  DMODEL, 1, 1);
    tf32_gemm_bl<<<dim3(DMODEL/TBN, BL/TBM), 256>>>(ff1, w2, b2, ff2, BL, DMODEL, FFDIM,  0, 0);

    // residual + LN2 -> out
    ln_reduce<<<dim3(256, BATCH), 256>>>(h, ff2, part);
    ln_stats <<<BATCH, 256>>>(part, stats);
    ln_apply <<<dim3(NPER/1024, BATCH), 256>>>(h, ff2, stats, out, (float*)0);
}

// round 11
// speedup vs baseline: 1.2182x; 1.2182x over previous
#include <cuda_runtime.h>
#include <cstdint>
#include <math.h>

#define BATCH   2
#define SEQLEN  2048
#define DMODEL  1024
#define NHEADS  16
#define DHEAD   64
#define FFDIM   4096
#define BL      (BATCH*SEQLEN)          // 4096
#define NPER    (SEQLEN*DMODEL)        // per-batch layernorm size

// ---------------- scratch (static device globals; no allocation allowed) ----
__device__ float g_q   [BL*DMODEL];
__device__ float g_k   [BL*DMODEL];
__device__ float g_v   [BL*DMODEL];
__device__ float g_attn[BL*DMODEL];
__device__ float g_h   [BL*DMODEL];
__device__ float g_ff1 [BL*FFDIM];
__device__ float g_ff2 [BL*DMODEL];
__device__ double g_part[BATCH*256*2];
__device__ float  g_stats[BATCH*2];

// --------------------------------------------------------- tf32 helpers ----
__device__ __forceinline__ uint32_t f2tf32(float x) {
    uint32_t u;
    asm("cvt.rna.tf32.f32 %0, %1;" : "=r"(u) : "f"(x));
    return u;
}

__device__ __forceinline__ void mma_tf32(float* c, const uint32_t* a, const uint32_t* b) {
    asm volatile(
        "mma.sync.aligned.m16n8k8.row.col.f32.tf32.tf32.f32 "
        "{%0,%1,%2,%3}, {%4,%5,%6,%7}, {%8,%9}, {%0,%1,%2,%3};"
        : "+f"(c[0]), "+f"(c[1]), "+f"(c[2]), "+f"(c[3])
        : "r"(a[0]), "r"(a[1]), "r"(a[2]), "r"(a[3]), "r"(b[0]), "r"(b[1]));
}

// software 2^t on FMA/ALU pipes (avoids MUFU bottleneck). t <= 0 expected.
__device__ __forceinline__ float exp2s(float t) {
    t = fmaxf(t, -126.0f);
    float z = t + 12582912.0f;                    // round-to-int magic (1.5*2^23)
    int ni = __float_as_int(z) - 0x4B400000;
    float f = t - (z - 12582912.0f);              // f in [-0.5, 0.5]
    float p = 1.3333558e-3f;
    p = fmaf(p, f, 9.6181291e-3f);
    p = fmaf(p, f, 5.5504109e-2f);
    p = fmaf(p, f, 2.4022651e-1f);
    p = fmaf(p, f, 6.9314718e-1f);
    p = fmaf(p, f, 1.0f);
    return p * __int_as_float((ni + 127) << 23);
}

// ------------------------------------------------------------- tf32 GEMM ----
// C[M,N] = A[M,K] @ W[K,N] + bias (+relu). Tensor cores via mma.sync tf32.
// R8 design (proven fastest): 128x128 tile, K-chunk 16, double-buffered smem,
// conversion to tf32 in registers on the load path.
#define TBM 128
#define TBN 128
#define TBK 16
#define ASTRIDE 20     // A smem [m][k] stride: (20*q + r) mod 32 covers all banks
#define WSTRIDE 136    // W smem [k][n] stride: bank = 8r + q, conflict-free

__device__ __forceinline__ void gemm_body(
    const float* __restrict__ A, const float* __restrict__ W,
    const float* __restrict__ bias, float* __restrict__ C,
    int M, int N, int K, int relu, int bx, int by,
    uint32_t* As /*[2][TBM*ASTRIDE]*/, uint32_t* Ws /*[2][TBK*WSTRIDE]*/)
{
    const int tid  = threadIdx.x;
    const int lane = tid & 31;
    const int warp = tid >> 5;
    const int q = lane >> 2, r = lane & 3;
    const int wr = warp >> 2, wc = warp & 3;
    const int bm = by * TBM, bn = bx * TBN;

    const int arow = tid >> 2;
    const int akc  = (tid & 3) * 4;
    const int wrow = tid >> 5;
    const int wcol = (tid & 31) * 4;

    const float* Ag = A + (size_t)(bm + arow) * K + akc;
    const float* Wg = W + (size_t)wrow * N + bn + wcol;

    float acc[4][4][4];
    #pragma unroll
    for (int i = 0; i < 4; i++)
        #pragma unroll
        for (int j = 0; j < 4; j++)
            #pragma unroll
            for (int e = 0; e < 4; e++) acc[i][j][e] = 0.f;

    float4 ra0, ra1, rw0, rw1;

    ra0 = *(const float4*)Ag;
    ra1 = *(const float4*)(Ag + (size_t)64 * K);
    rw0 = *(const float4*)Wg;
    rw1 = *(const float4*)(Wg + (size_t)8 * N);
    Ag += TBK;
    Wg += (size_t)TBK * N;
    {
        uint4 pa0 = make_uint4(f2tf32(ra0.x), f2tf32(ra0.y), f2tf32(ra0.z), f2tf32(ra0.w));
        uint4 pa1 = make_uint4(f2tf32(ra1.x), f2tf32(ra1.y), f2tf32(ra1.z), f2tf32(ra1.w));
        uint4 pw0 = make_uint4(f2tf32(rw0.x), f2tf32(rw0.y), f2tf32(rw0.z), f2tf32(rw0.w));
        uint4 pw1 = make_uint4(f2tf32(rw1.x), f2tf32(rw1.y), f2tf32(rw1.z), f2tf32(rw1.w));
        *(uint4*)&As[arow*ASTRIDE + akc]        = pa0;
        *(uint4*)&As[(arow + 64)*ASTRIDE + akc] = pa1;
        *(uint4*)&Ws[wrow*WSTRIDE + wcol]       = pw0;
        *(uint4*)&Ws[(wrow + 8)*WSTRIDE + wcol] = pw1;
    }
    __syncthreads();

    const int nchunk = K / TBK;
    #pragma unroll 1
    for (int c = 0; c < nchunk; c++) {
        const int cur = c & 1;
        const bool has_next = (c + 1 < nchunk);
        const uint32_t* Ab = As + cur * (TBM*ASTRIDE);
        const uint32_t* Wb = Ws + cur * (TBK*WSTRIDE);

        if (has_next) {
            ra0 = *(const float4*)Ag;
            ra1 = *(const float4*)(Ag + (size_t)64 * K);
            rw0 = *(const float4*)Wg;
            rw1 = *(const float4*)(Wg + (size_t)8 * N);
            Ag += TBK;
            Wg += (size_t)TBK * N;
        }

        #pragma unroll
        for (int k8 = 0; k8 < TBK; k8 += 8) {
            uint32_t af[4][4], bf[4][2];
            #pragma unroll
            for (int tm = 0; tm < 4; tm++) {
                const int m = wr*64 + tm*16 + q;
                af[tm][0] = Ab[m*ASTRIDE + k8 + r];
                af[tm][1] = Ab[(m + 8)*ASTRIDE + k8 + r];
                af[tm][2] = Ab[m*ASTRIDE + k8 + r + 4];
                af[tm][3] = Ab[(m + 8)*ASTRIDE + k8 + r + 4];
            }
            #pragma unroll
            for (int tn = 0; tn < 4; tn++) {
                const int n = wc*32 + tn*8 + q;
                bf[tn][0] = Wb[(k8 + r)*WSTRIDE + n];
                bf[tn][1] = Wb[(k8 + r + 4)*WSTRIDE + n];
            }
            #pragma unroll
            for (int tm = 0; tm < 4; tm++)
                #pragma unroll
                for (int tn = 0; tn < 4; tn++)
                    mma_tf32(acc[tm][tn], af[tm], bf[tn]);
        }

        if (has_next) {
            uint32_t* An = As + (cur^1) * (TBM*ASTRIDE);
            uint32_t* Wn = Ws + (cur^1) * (TBK*WSTRIDE);
            uint4 pa0 = make_uint4(f2tf32(ra0.x), f2tf32(ra0.y), f2tf32(ra0.z), f2tf32(ra0.w));
            uint4 pa1 = make_uint4(f2tf32(ra1.x), f2tf32(ra1.y), f2tf32(ra1.z), f2tf32(ra1.w));
            uint4 pw0 = make_uint4(f2tf32(rw0.x), f2tf32(rw0.y), f2tf32(rw0.z), f2tf32(rw0.w));
            uint4 pw1 = make_uint4(f2tf32(rw1.x), f2tf32(rw1.y), f2tf32(rw1.z), f2tf32(rw1.w));
            *(uint4*)&An[arow*ASTRIDE + akc]        = pa0;
            *(uint4*)&An[(arow + 64)*ASTRIDE + akc] = pa1;
            *(uint4*)&Wn[wrow*WSTRIDE + wcol]       = pw0;
            *(uint4*)&Wn[(wrow + 8)*WSTRIDE + wcol] = pw1;
        }
        __syncthreads();
    }

    #pragma unroll
    for (int tm = 0; tm < 4; tm++) {
        const int row = bm + wr*64 + tm*16 + q;
        #pragma unroll
        for (int tn = 0; tn < 4; tn++) {
            const int col = bn + wc*32 + tn*8 + 2*r;
            const float2 bv = *(const float2*)(bias + col);
            float2 c01, c23;
            c01.x = acc[tm][tn][0] + bv.x; c01.y = acc[tm][tn][1] + bv.y;
            c23.x = acc[tm][tn][2] + bv.x; c23.y = acc[tm][tn][3] + bv.y;
            if (relu) {
                c01.x = fmaxf(c01.x, 0.f); c01.y = fmaxf(c01.y, 0.f);
                c23.x = fmaxf(c23.x, 0.f); c23.y = fmaxf(c23.y, 0.f);
            }
            *(float2*)(C + (size_t)row*N + col)       = c01;
            *(float2*)(C + (size_t)(row + 8)*N + col) = c23;
        }
    }
}

__global__ __launch_bounds__(256) void tf32_gemm_bias(
    const float* __restrict__ A, const float* __restrict__ W,
    const float* __restrict__ bias, float* __restrict__ C,
    int M, int N, int K, int relu)
{
    __shared__ uint32_t As[2*TBM*ASTRIDE];
    __shared__ uint32_t Ws[2*TBK*WSTRIDE];
    gemm_body(A, W, bias, C, M, N, K, relu, blockIdx.x, blockIdx.y, As, Ws);
}

// fused QKV: blockIdx.z selects projection (one packed launch, 768 CTAs)
__global__ __launch_bounds__(256) void qkv_gemm(
    const float* __restrict__ A,
    const float* __restrict__ wq, const float* __restrict__ bq, float* __restrict__ q,
    const float* __restrict__ wk, const float* __restrict__ bk, float* __restrict__ k,
    const float* __restrict__ wv, const float* __restrict__ bv, float* __restrict__ v)
{
    __shared__ uint32_t As[2*TBM*ASTRIDE];
    __shared__ uint32_t Ws[2*TBK*WSTRIDE];
    const int z = blockIdx.z;
    const float* W    = (z == 0) ? wq : (z == 1) ? wk : wv;
    const float* bias = (z == 0) ? bq : (z == 1) ? bk : bv;
    float*       C    = (z == 0) ? q  : (z == 1) ? k  : v;
    gemm_body(A, W, bias, C, BL, DMODEL, DMODEL, 0, blockIdx.x, blockIdx.y, As, Ws);
}

// --------------------------------------- tensor-core flash attention -------
#define FA_BR 128
#define FA_BC 32
#define PS_STRIDE 36
#define KS_STRIDE 40
#define VS_STRIDE 72

__global__ __launch_bounds__(256) void flash_attn_tc(
    const float* __restrict__ Q, const float* __restrict__ K,
    const float* __restrict__ V, float* __restrict__ O)
{
    __shared__ uint32_t KsT[64*KS_STRIDE];
    __shared__ uint32_t Vs [FA_BC*VS_STRIDE];
    __shared__ uint32_t Ps [FA_BR*PS_STRIDE];

    const int tid  = threadIdx.x;
    const int lane = tid & 31;
    const int warp = tid >> 5;
    const int qg = lane >> 2, r = lane & 3;
    const int b = blockIdx.z, h = blockIdx.y;
    const int q0 = blockIdx.x * FA_BR;
    const size_t base = ((size_t)b * SEQLEN) * DMODEL + h * DHEAD;

    const int mrow = warp*16 + qg;

    uint32_t qf[8][4];
    {
        const float* qp  = Q + base + (size_t)(q0 + mrow) * DMODEL;
        const float* qp8 = qp + (size_t)8 * DMODEL;
        #pragma unroll
        for (int ks = 0; ks < 8; ks++) {
            qf[ks][0] = f2tf32(__ldg(qp  + ks*8 + r));
            qf[ks][1] = f2tf32(__ldg(qp8 + ks*8 + r));
            qf[ks][2] = f2tf32(__ldg(qp  + ks*8 + r + 4));
            qf[ks][3] = f2tf32(__ldg(qp8 + ks*8 + r + 4));
        }
    }

    float oc[8][4];
    #pragma unroll
    for (int nf = 0; nf < 8; nf++)
        #pragma unroll
        for (int e = 0; e < 4; e++) oc[nf][e] = 0.f;
    float m0 = -INFINITY, m1 = -INFINITY, l0 = 0.f, l1 = 0.f;

    const int vrow = tid >> 3;
    const int vc0  = (tid & 7) * 4;

    const float SCL = 0.125f * 1.44269504f;

    for (int kt = 0; kt < SEQLEN/FA_BC; kt++) {
        __syncthreads();
        {
            const float* kp = K + base + (size_t)(kt*FA_BC + lane)*DMODEL + warp*8;
            float4 k0 = *(const float4*)kp;
            float4 k1 = *(const float4*)(kp + 4);
            KsT[(warp*8+0)*KS_STRIDE + lane] = f2tf32(k0.x);
            KsT[(warp*8+1)*KS_STRIDE + lane] = f2tf32(k0.y);
            KsT[(warp*8+2)*KS_STRIDE + lane] = f2tf32(k0.z);
            KsT[(warp*8+3)*KS_STRIDE + lane] = f2tf32(k0.w);
            KsT[(warp*8+4)*KS_STRIDE + lane] = f2tf32(k1.x);
            KsT[(warp*8+5)*KS_STRIDE + lane] = f2tf32(k1.y);
            KsT[(warp*8+6)*KS_STRIDE + lane] = f2tf32(k1.z);
            KsT[(warp*8+7)*KS_STRIDE + lane] = f2tf32(k1.w);
            const float* vp = V + base + (size_t)(kt*FA_BC + vrow)*DMODEL + vc0;
            float4 v0 = *(const float4*)vp;
            float4 v1 = *(const float4*)(vp + 32);
            *(uint4*)&Vs[vrow*VS_STRIDE + vc0] =
                make_uint4(f2tf32(v0.x), f2tf32(v0.y), f2tf32(v0.z), f2tf32(v0.w));
            *(uint4*)&Vs[vrow*VS_STRIDE + vc0 + 32] =
                make_uint4(f2tf32(v1.x), f2tf32(v1.y), f2tf32(v1.z), f2tf32(v1.w));
        }
        __syncthreads();

        float sc[4][4];
        #pragma unroll
        for (int nf = 0; nf < 4; nf++)
            #pragma unroll
            for (int e = 0; e < 4; e++) sc[nf][e] = 0.f;

        #pragma unroll
        for (int ks = 0; ks < 8; ks++) {
            uint32_t bfr[4][2];
            #pragma unroll
            for (int nf = 0; nf < 4; nf++) {
                bfr[nf][0] = KsT[(ks*8 + r)*KS_STRIDE + nf*8 + qg];
                bfr[nf][1] = KsT[(ks*8 + r + 4)*KS_STRIDE + nf*8 + qg];
            }
            #pragma unroll
            for (int nf = 0; nf < 4; nf++)
                mma_tf32(sc[nf], qf[ks], bfr[nf]);
        }

        float rm0 = -INFINITY, rm1 = -INFINITY;
        #pragma unroll
        for (int nf = 0; nf < 4; nf++) {
            rm0 = fmaxf(rm0, fmaxf(sc[nf][0], sc[nf][1]));
            rm1 = fmaxf(rm1, fmaxf(sc[nf][2], sc[nf][3]));
        }
        rm0 = fmaxf(rm0, __shfl_xor_sync(0xffffffffu, rm0, 1));
        rm0 = fmaxf(rm0, __shfl_xor_sync(0xffffffffu, rm0, 2));
        rm1 = fmaxf(rm1, __shfl_xor_sync(0xffffffffu, rm1, 1));
        rm1 = fmaxf(rm1, __shfl_xor_sync(0xffffffffu, rm1, 2));

        const float mt0 = fmaxf(m0, rm0 * SCL);
        const float mt1 = fmaxf(m1, rm1 * SCL);
        const float c0 = exp2s(m0 - mt0);
        const float c1 = exp2s(m1 - mt1);
        m0 = mt0; m1 = mt1;

        float rs0 = 0.f, rs1 = 0.f;
        #pragma unroll
        for (int nf = 0; nf < 4; nf++) {
            const float p0 = exp2s(fmaf(sc[nf][0], SCL, -mt0));
            const float p1 = exp2s(fmaf(sc[nf][1], SCL, -mt0));
            const float p2 = exp2s(fmaf(sc[nf][2], SCL, -mt1));
            const float p3 = exp2s(fmaf(sc[nf][3], SCL, -mt1));
            rs0 += p0 + p1;
            rs1 += p2 + p3;
            const int colw = nf*8 + 2*r;
            *(uint2*)&Ps[(mrow)*PS_STRIDE + colw]     = make_uint2(f2tf32(p0), f2tf32(p1));
            *(uint2*)&Ps[(mrow + 8)*PS_STRIDE + colw] = make_uint2(f2tf32(p2), f2tf32(p3));
        }
        rs0 += __shfl_xor_sync(0xffffffffu, rs0, 1);
        rs0 += __shfl_xor_sync(0xffffffffu, rs0, 2);
        rs1 += __shfl_xor_sync(0xffffffffu, rs1, 1);
        rs1 += __shfl_xor_sync(0xffffffffu, rs1, 2);
        l0 = l0*c0 + rs0;
        l1 = l1*c1 + rs1;

        #pragma unroll
        for (int nf = 0; nf < 8; nf++) {
            oc[nf][0] *= c0; oc[nf][1] *= c0;
            oc[nf][2] *= c1; oc[nf][3] *= c1;
        }
        __syncwarp();

        #pragma unroll
        for (int ks = 0; ks < 4; ks++) {
            uint32_t af[4];
            af[0] = Ps[(mrow)*PS_STRIDE     + ks*8 + r];
            af[1] = Ps[(mrow + 8)*PS_STRIDE + ks*8 + r];
            af[2] = Ps[(mrow)*PS_STRIDE     + ks*8 + r + 4];
            af[3] = Ps[(mrow + 8)*PS_STRIDE + ks*8 + r + 4];
            #pragma unroll
            for (int nf = 0; nf < 8; nf++) {
                uint32_t bf2[2];
                bf2[0] = Vs[(ks*8 + r)*VS_STRIDE + nf*8 + qg];
                bf2[1] = Vs[(ks*8 + r + 4)*VS_STRIDE + nf*8 + qg];
                mma_tf32(oc[nf], af, bf2);
            }
        }
    }

    const float inv0 = 1.0f / l0;
    const float inv1 = 1.0f / l1;
    float* op  = O + base + (size_t)(q0 + mrow) * DMODEL;
    float* op8 = op + (size_t)8 * DMODEL;
    #pragma unroll
    for (int nf = 0; nf < 8; nf++) {
        const int col = nf*8 + 2*r;
        *(float2*)(op  + col) = make_float2(oc[nf][0]*inv0, oc[nf][1]*inv0);
        *(float2*)(op8 + col) = make_float2(oc[nf][2]*inv1, oc[nf][3]*inv1);
    }
}

// ------------------------------------------------------------ layernorm ----
// fp32 inner accumulation (each thread covers only 32 elements -> error ~32eps);
// cross-thread/block reduction in double. Removes the FP64-pipe bottleneck
// measured in R10 (ln_reduce was fp64-throughput-bound at 37us).
__global__ __launch_bounds__(256) void ln_reduce(
    const float* __restrict__ a, const float* __restrict__ b,
    double* __restrict__ part)
{
    const int batch = blockIdx.y;
    const float* pa = a + (size_t)batch * NPER;
    const float* pb = b + (size_t)batch * NPER;
    float s = 0.f, ss = 0.f;
    const size_t stride4 = (size_t)gridDim.x * blockDim.x;      // float4 stride
    for (size_t i = blockIdx.x*blockDim.x + threadIdx.x; i < NPER/4; i += stride4) {
        float4 va = *(const float4*)(pa + i*4);
        float4 vb = *(const float4*)(pb + i*4);
        float z0 = va.x + vb.x, z1 = va.y + vb.y;
        float z2 = va.z + vb.z, z3 = va.w + vb.w;
        s  += (z0 + z1) + (z2 + z3);
        ss = fmaf(z0, z0, ss); ss = fmaf(z1, z1, ss);
        ss = fmaf(z2, z2, ss); ss = fmaf(z3, z3, ss);
    }
    __shared__ double sh[512];
    int tid = threadIdx.x;
    sh[tid] = (double)s; sh[256 + tid] = (double)ss;
    __syncthreads();
    for (int st = 128; st > 0; st >>= 1) {
        if (tid < st) { sh[tid] += sh[tid+st]; sh[256+tid] += sh[256+tid+st]; }
        __syncthreads();
    }
    if (tid == 0) {
        part[(batch*256 + blockIdx.x)*2 + 0] = sh[0];
        part[(batch*256 + blockIdx.x)*2 + 1] = sh[256];
    }
}

__global__ __launch_bounds__(256) void ln_stats(
    const double* __restrict__ part, float* __restrict__ stats)
{
    const int batch = blockIdx.x;
    int tid = threadIdx.x;
    __shared__ double sh[512];
    sh[tid]       = part[(batch*256 + tid)*2 + 0];
    sh[256 + tid] = part[(batch*256 + tid)*2 + 1];
    __syncthreads();
    for (int st = 128; st > 0; st >>= 1) {
        if (tid < st) { sh[tid] += sh[tid+st]; sh[256+tid] += sh[256+tid+st]; }
        __syncthreads();
    }
    if (tid == 0) {
        double mean = sh[0] / (double)NPER;
        double var  = sh[256] / (double)NPER - mean*mean + 1e-5;
        stats[batch*2 + 0] = (float)mean;
        stats[batch*2 + 1] = (float)(1.0 / sqrt(var));
    }
}

__global__ __launch_bounds__(256) void ln_apply(
    const float* __restrict__ a, const float* __restrict__ b,
    const float* __restrict__ stats, float* __restrict__ out)
{
    const int batch = blockIdx.y;
    const float mean = stats[batch*2 + 0];
    const float inv  = stats[batch*2 + 1];
    size_t off = (size_t)batch * NPER + (size_t)(blockIdx.x*blockDim.x + threadIdx.x)*4;
    float4 va = *(const float4*)(a + off);
    float4 vb = *(const float4*)(b + off);
    float4 o;
    o.x = (va.x + vb.x - mean) * inv;
    o.y = (va.y + vb.y - mean) * inv;
    o.z = (va.z + vb.z - mean) * inv;
    o.w = (va.w + vb.w - mean) * inv;
    *(float4*)(out + off) = o;
}

// -------------------------------------------------------------- launch -----
extern "C" void kernel_launch(void* const* d_in, const int* in_sizes, int n_in,
                              void* d_out, int out_size)
{
    const float* x  = (const float*)d_in[0];
    const float* wq = (const float*)d_in[1];
    const float* bq = (const float*)d_in[2];
    const float* wk = (const float*)d_in[3];
    const float* bk = (const float*)d_in[4];
    const float* wv = (const float*)d_in[5];
    const float* bv = (const float*)d_in[6];
    const float* w1 = (const float*)d_in[7];
    const float* b1 = (const float*)d_in[8];
    const float* w2 = (const float*)d_in[9];
    const float* b2 = (const float*)d_in[10];
    float* out = (float*)d_out;

    float *q, *k, *v, *attn, *h, *ff1, *ff2, *stats;
    double* part;
    cudaGetSymbolAddress((void**)&q,    g_q);
    cudaGetSymbolAddress((void**)&k,    g_k);
    cudaGetSymbolAddress((void**)&v,    g_v);
    cudaGetSymbolAddress((void**)&attn, g_attn);
    cudaGetSymbolAddress((void**)&h,    g_h);
    cudaGetSymbolAddress((void**)&ff1,  g_ff1);
    cudaGetSymbolAddress((void**)&ff2,  g_ff2);
    cudaGetSymbolAddress((void**)&part, g_part);
    cudaGetSymbolAddress((void**)&stats, g_stats);

    // fused QKV projections (tensor cores, tf32) — one packed launch
    qkv_gemm<<<dim3(DMODEL/TBN, BL/TBM, 3), 256>>>(
        x, wq, bq, q, wk, bk, k, wv, bv, v);

    // attention (tensor cores + software exp2)
    flash_attn_tc<<<dim3(SEQLEN/FA_BR, NHEADS, BATCH), 256>>>(q, k, v, attn);

    // residual + LN1 -> h
    ln_reduce<<<dim3(256, BATCH), 256>>>(x, attn, part);
    ln_stats <<<BATCH, 256>>>(part, stats);
    ln_apply <<<dim3(NPER/1024, BATCH), 256>>>(x, attn, stats, h);

    // FFN (tensor cores, tf32)
    tf32_gemm_bias<<<dim3(FFDIM/TBN,  BL/TBM), 256>>>(h,   w1, b1, ff1, BL, FFDIM,  DMODEL, 1);
    tf32_gemm_bias<<<dim3(DMODEL/TBN, BL/TBM), 256>>>(ff1, w2, b2, ff2, BL, DMODEL, FFDIM,  0);

    // residual + LN2 -> out
    ln_reduce<<<dim3(256, BATCH), 256>>>(h, ff2, part);
    ln_stats <<<BATCH, 256>>>(part, stats);
    ln_apply <<<dim3(NPER/1024, BATCH), 256>>>(h, ff2, stats, out);
}

// round 13
// speedup vs baseline: 1.2565x; 1.0315x over previous
#include <cuda_runtime.h>
#include <cstdint>
#include <math.h>

#define BATCH   2
#define SEQLEN  2048
#define DMODEL  1024
#define NHEADS  16
#define DHEAD   64
#define FFDIM   4096
#define BL      (BATCH*SEQLEN)          // 4096
#define NPER    (SEQLEN*DMODEL)        // per-batch layernorm size

// ---------------- scratch (static device globals; no allocation allowed) ----
__device__ float g_q   [BL*DMODEL];
__device__ float g_k   [BL*DMODEL];
__device__ float g_v   [BL*DMODEL];
__device__ float g_attn[BL*DMODEL];
__device__ float g_h   [BL*DMODEL];
__device__ float g_ff1 [BL*FFDIM];
__device__ float g_ff2 [BL*DMODEL];
__device__ double g_part[BATCH*256*2];
__device__ float  g_stats[BATCH*2];

// --------------------------------------------------------- tf32 helpers ----
__device__ __forceinline__ uint32_t f2tf32(float x) {
    uint32_t u;
    asm("cvt.rna.tf32.f32 %0, %1;" : "=r"(u) : "f"(x));
    return u;
}

__device__ __forceinline__ void mma_tf32(float* c, const uint32_t* a, const uint32_t* b) {
    asm volatile(
        "mma.sync.aligned.m16n8k8.row.col.f32.tf32.tf32.f32 "
        "{%0,%1,%2,%3}, {%4,%5,%6,%7}, {%8,%9}, {%0,%1,%2,%3};"
        : "+f"(c[0]), "+f"(c[1]), "+f"(c[2]), "+f"(c[3])
        : "r"(a[0]), "r"(a[1]), "r"(a[2]), "r"(a[3]), "r"(b[0]), "r"(b[1]));
}

__device__ __forceinline__ void cp_async16(uint32_t saddr, const void* gptr) {
    asm volatile("cp.async.ca.shared.global [%0], [%1], 16;" :: "r"(saddr), "l"(gptr));
}
__device__ __forceinline__ void cp_async_commit() {
    asm volatile("cp.async.commit_group;");
}
__device__ __forceinline__ void cp_async_wait0() {
    asm volatile("cp.async.wait_group 0;");
}

// software 2^t on FMA/ALU pipes (avoids MUFU bottleneck). t <= 0 expected.
__device__ __forceinline__ float exp2s(float t) {
    t = fmaxf(t, -126.0f);
    float z = t + 12582912.0f;                    // round-to-int magic (1.5*2^23)
    int ni = __float_as_int(z) - 0x4B400000;
    float f = t - (z - 12582912.0f);              // f in [-0.5, 0.5]
    float p = 1.3333558e-3f;
    p = fmaf(p, f, 9.6181291e-3f);
    p = fmaf(p, f, 5.5504109e-2f);
    p = fmaf(p, f, 2.4022651e-1f);
    p = fmaf(p, f, 6.9314718e-1f);
    p = fmaf(p, f, 1.0f);
    return p * __int_as_float((ni + 127) << 23);
}

// ------------------------------------------------------------- tf32 GEMM ----
// C[M,N] = A[M,K] @ W[K,N] + bias (+relu) (+tf32-round on store).
#define TBM 128
#define TBN 128
#define TBK 16
#define ASTRIDE 20     // A smem [m][k] stride: (20*q + r) mod 32 covers all banks
#define WSTRIDE 136    // W smem [k][n] stride: bank = 8r + q, conflict-free

__device__ __forceinline__ void gemm_body(
    const float* __restrict__ A, const float* __restrict__ W,
    const float* __restrict__ bias, float* __restrict__ C,
    int M, int N, int K, int relu, int rnd, int bx, int by,
    uint32_t* As /*[2][TBM*ASTRIDE]*/, uint32_t* Ws /*[2][TBK*WSTRIDE]*/)
{
    const int tid  = threadIdx.x;
    const int lane = tid & 31;
    const int warp = tid >> 5;
    const int q = lane >> 2, r = lane & 3;
    const int wr = warp >> 2, wc = warp & 3;
    const int bm = by * TBM, bn = bx * TBN;

    const int arow = tid >> 2;
    const int akc  = (tid & 3) * 4;
    const int wrow = tid >> 5;
    const int wcol = (tid & 31) * 4;

    const float* Ag = A + (size_t)(bm + arow) * K + akc;
    const float* Wg = W + (size_t)wrow * N + bn + wcol;

    float acc[4][4][4];
    #pragma unroll
    for (int i = 0; i < 4; i++)
        #pragma unroll
        for (int j = 0; j < 4; j++)
            #pragma unroll
            for (int e = 0; e < 4; e++) acc[i][j][e] = 0.f;

    float4 ra0, ra1, rw0, rw1;

    ra0 = *(const float4*)Ag;
    ra1 = *(const float4*)(Ag + (size_t)64 * K);
    rw0 = *(const float4*)Wg;
    rw1 = *(const float4*)(Wg + (size_t)8 * N);
    Ag += TBK;
    Wg += (size_t)TBK * N;
    {
        uint4 pa0 = make_uint4(f2tf32(ra0.x), f2tf32(ra0.y), f2tf32(ra0.z), f2tf32(ra0.w));
        uint4 pa1 = make_uint4(f2tf32(ra1.x), f2tf32(ra1.y), f2tf32(ra1.z), f2tf32(ra1.w));
        uint4 pw0 = make_uint4(f2tf32(rw0.x), f2tf32(rw0.y), f2tf32(rw0.z), f2tf32(rw0.w));
        uint4 pw1 = make_uint4(f2tf32(rw1.x), f2tf32(rw1.y), f2tf32(rw1.z), f2tf32(rw1.w));
        *(uint4*)&As[arow*ASTRIDE + akc]        = pa0;
        *(uint4*)&As[(arow + 64)*ASTRIDE + akc] = pa1;
        *(uint4*)&Ws[wrow*WSTRIDE + wcol]       = pw0;
        *(uint4*)&Ws[(wrow + 8)*WSTRIDE + wcol] = pw1;
    }
    __syncthreads();

    const int nchunk = K / TBK;
    #pragma unroll 1
    for (int c = 0; c < nchunk; c++) {
        const int cur = c & 1;
        const bool has_next = (c + 1 < nchunk);
        const uint32_t* Ab = As + cur * (TBM*ASTRIDE);
        const uint32_t* Wb = Ws + cur * (TBK*WSTRIDE);

        if (has_next) {
            ra0 = *(const float4*)Ag;
            ra1 = *(const float4*)(Ag + (size_t)64 * K);
            rw0 = *(const float4*)Wg;
            rw1 = *(const float4*)(Wg + (size_t)8 * N);
            Ag += TBK;
            Wg += (size_t)TBK * N;
        }

        #pragma unroll
        for (int k8 = 0; k8 < TBK; k8 += 8) {
            uint32_t af[4][4], bf[4][2];
            #pragma unroll
            for (int tm = 0; tm < 4; tm++) {
                const int m = wr*64 + tm*16 + q;
                af[tm][0] = Ab[m*ASTRIDE + k8 + r];
                af[tm][1] = Ab[(m + 8)*ASTRIDE + k8 + r];
                af[tm][2] = Ab[m*ASTRIDE + k8 + r + 4];
                af[tm][3] = Ab[(m + 8)*ASTRIDE + k8 + r + 4];
            }
            #pragma unroll
            for (int tn = 0; tn < 4; tn++) {
                const int n = wc*32 + tn*8 + q;
                bf[tn][0] = Wb[(k8 + r)*WSTRIDE + n];
                bf[tn][1] = Wb[(k8 + r + 4)*WSTRIDE + n];
            }
            #pragma unroll
            for (int tm = 0; tm < 4; tm++)
                #pragma unroll
                for (int tn = 0; tn < 4; tn++)
                    mma_tf32(acc[tm][tn], af[tm], bf[tn]);
        }

        if (has_next) {
            uint32_t* An = As + (cur^1) * (TBM*ASTRIDE);
            uint32_t* Wn = Ws + (cur^1) * (TBK*WSTRIDE);
            uint4 pa0 = make_uint4(f2tf32(ra0.x), f2tf32(ra0.y), f2tf32(ra0.z), f2tf32(ra0.w));
            uint4 pa1 = make_uint4(f2tf32(ra1.x), f2tf32(ra1.y), f2tf32(ra1.z), f2tf32(ra1.w));
            uint4 pw0 = make_uint4(f2tf32(rw0.x), f2tf32(rw0.y), f2tf32(rw0.z), f2tf32(rw0.w));
            uint4 pw1 = make_uint4(f2tf32(rw1.x), f2tf32(rw1.y), f2tf32(rw1.z), f2tf32(rw1.w));
            *(uint4*)&An[arow*ASTRIDE + akc]        = pa0;
            *(uint4*)&An[(arow + 64)*ASTRIDE + akc] = pa1;
            *(uint4*)&Wn[wrow*WSTRIDE + wcol]       = pw0;
            *(uint4*)&Wn[(wrow + 8)*WSTRIDE + wcol] = pw1;
        }
        __syncthreads();
    }

    #pragma unroll
    for (int tm = 0; tm < 4; tm++) {
        const int row = bm + wr*64 + tm*16 + q;
        #pragma unroll
        for (int tn = 0; tn < 4; tn++) {
            const int col = bn + wc*32 + tn*8 + 2*r;
            const float2 bv = *(const float2*)(bias + col);
            float c0 = acc[tm][tn][0] + bv.x, c1 = acc[tm][tn][1] + bv.y;
            float c2 = acc[tm][tn][2] + bv.x, c3 = acc[tm][tn][3] + bv.y;
            if (relu) {
                c0 = fmaxf(c0, 0.f); c1 = fmaxf(c1, 0.f);
                c2 = fmaxf(c2, 0.f); c3 = fmaxf(c3, 0.f);
            }
            if (rnd) {   // pre-round for cp.async raw-bit consumers (idempotent)
                c0 = __uint_as_float(f2tf32(c0)); c1 = __uint_as_float(f2tf32(c1));
                c2 = __uint_as_float(f2tf32(c2)); c3 = __uint_as_float(f2tf32(c3));
            }
            *(float2*)(C + (size_t)row*N + col)       = make_float2(c0, c1);
            *(float2*)(C + (size_t)(row + 8)*N + col) = make_float2(c2, c3);
        }
    }
}

__global__ __launch_bounds__(256) void tf32_gemm_bias(
    const float* __restrict__ A, const float* __restrict__ W,
    const float* __restrict__ bias, float* __restrict__ C,
    int M, int N, int K, int relu)
{
    __shared__ uint32_t As[2*TBM*ASTRIDE];
    __shared__ uint32_t Ws[2*TBK*WSTRIDE];
    gemm_body(A, W, bias, C, M, N, K, relu, 0, blockIdx.x, blockIdx.y, As, Ws);
}

// fused QKV: blockIdx.z selects projection; outputs tf32-pre-rounded
__global__ __launch_bounds__(256) void qkv_gemm(
    const float* __restrict__ A,
    const float* __restrict__ wq, const float* __restrict__ bq, float* __restrict__ q,
    const float* __restrict__ wk, const float* __restrict__ bk, float* __restrict__ k,
    const float* __restrict__ wv, const float* __restrict__ bv, float* __restrict__ v)
{
    __shared__ uint32_t As[2*TBM*ASTRIDE];
    __shared__ uint32_t Ws[2*TBK*WSTRIDE];
    const int z = blockIdx.z;
    const float* W    = (z == 0) ? wq : (z == 1) ? wk : wv;
    const float* bias = (z == 0) ? bq : (z == 1) ? bk : bv;
    float*       C    = (z == 0) ? q  : (z == 1) ? k  : v;
    gemm_body(A, W, bias, C, BL, DMODEL, DMODEL, 0, 1, blockIdx.x, blockIdx.y, As, Ws);
}

// --------------------------------------- tensor-core flash attention -------
// cp.async pipelined: K double-buffered (issued right after S-MMA), V issued
// one tile ahead (after PV sync). K/V arrive PRE-ROUNDED to tf32 from the QKV
// epilogue, so raw-bit cp.async copies are valid tf32.
#define FA_BR 128
#define FA_BC 32
#define PS_STRIDE 36    // [qrow][key]: A-frag read bank = 4q + r, conflict-free
#define KN_STRIDE 68    // [key][dh]:   B-frag read bank = 4qg + r, conflict-free
#define VS_STRIDE 72    // [key][dh]:   B-frag read bank = 8r + qg, conflict-free

__global__ __launch_bounds__(256) void flash_attn_tc(
    const float* __restrict__ Q, const float* __restrict__ K,
    const float* __restrict__ V, float* __restrict__ O)
{
    __shared__ uint32_t Ks[2][FA_BC*KN_STRIDE];   // 17408 B
    __shared__ uint32_t Vs [FA_BC*VS_STRIDE];     //  9216 B
    __shared__ uint32_t Ps [FA_BR*PS_STRIDE];     // 18432 B

    const int tid  = threadIdx.x;
    const int lane = tid & 31;
    const int warp = tid >> 5;
    const int qg = lane >> 2, r = lane & 3;
    const int b = blockIdx.z, h = blockIdx.y;
    const int q0 = blockIdx.x * FA_BR;
    const size_t base = ((size_t)b * SEQLEN) * DMODEL + h * DHEAD;

    const int mrow = warp*16 + qg;

    // loader mapping: key = tid>>3 (0..31), col0 = (tid&7)*8 (two 16B chunks)
    const int lkey = tid >> 3;
    const int lcol = (tid & 7) * 8;
    const uint32_t ks_dst0 = (uint32_t)__cvta_generic_to_shared(&Ks[0][lkey*KN_STRIDE + lcol]);
    const uint32_t ks_dst1 = (uint32_t)__cvta_generic_to_shared(&Ks[1][lkey*KN_STRIDE + lcol]);
    const uint32_t vs_dst  = (uint32_t)__cvta_generic_to_shared(&Vs[lkey*VS_STRIDE + lcol]);
    const float* kg = K + base + (size_t)lkey * DMODEL + lcol;
    const float* vg = V + base + (size_t)lkey * DMODEL + lcol;

    // Q fragments straight from gmem (once per block)
    uint32_t qf[8][4];
    {
        const float* qp  = Q + base + (size_t)(q0 + mrow) * DMODEL;
        const float* qp8 = qp + (size_t)8 * DMODEL;
        #pragma unroll
        for (int ks = 0; ks < 8; ks++) {
            qf[ks][0] = f2tf32(__ldg(qp  + ks*8 + r));
            qf[ks][1] = f2tf32(__ldg(qp8 + ks*8 + r));
            qf[ks][2] = f2tf32(__ldg(qp  + ks*8 + r + 4));
            qf[ks][3] = f2tf32(__ldg(qp8 + ks*8 + r + 4));
        }
    }

    float oc[8][4];
    #pragma unroll
    for (int nf = 0; nf < 8; nf++)
        #pragma unroll
        for (int e = 0; e < 4; e++) oc[nf][e] = 0.f;
    float m0 = -INFINITY, m1 = -INFINITY, l0 = 0.f, l1 = 0.f;

    const float SCL = 0.125f * 1.44269504f;   // 1/sqrt(dh) * log2(e)

    // prologue: tile 0 K+V in flight
    cp_async16(ks_dst0, kg);
    cp_async16(ks_dst0 + 16, kg + 4);
    cp_async16(vs_dst, vg);
    cp_async16(vs_dst + 16, vg + 4);
    cp_async_commit();

    const int ntiles = SEQLEN / FA_BC;
    #pragma unroll 1
    for (int kt = 0; kt < ntiles; kt++) {
        const int cur = kt & 1;
        const bool has_next = (kt + 1 < ntiles);
        const uint32_t* Kb = Ks[cur];

        cp_async_wait0();      // K(kt) + V(kt) resident
        __syncthreads();

        // S = Q @ K^T : 8 k-steps (dh) x 4 n-frags (keys)
        float sc[4][4];
        #pragma unroll
        for (int nf = 0; nf < 4; nf++)
            #pragma unroll
            for (int e = 0; e < 4; e++) sc[nf][e] = 0.f;

        #pragma unroll
        for (int ks = 0; ks < 8; ks++) {
            uint32_t bfr[4][2];
            #pragma unroll
            for (int nf = 0; nf < 4; nf++) {
                bfr[nf][0] = Kb[(nf*8 + qg)*KN_STRIDE + ks*8 + r];
                bfr[nf][1] = Kb[(nf*8 + qg)*KN_STRIDE + ks*8 + r + 4];
            }
            #pragma unroll
            for (int nf = 0; nf < 4; nf++)
                mma_tf32(sc[nf], qf[ks], bfr[nf]);
        }

        // prefetch next K into the other buffer (disjoint from all readers)
        if (has_next) {
            const float* kn = kg + (size_t)(kt + 1) * FA_BC * DMODEL;
            const uint32_t kd = cur ? ks_dst0 : ks_dst1;
            cp_async16(kd, kn);
            cp_async16(kd + 16, kn + 4);
            cp_async_commit();
        }

        // online softmax in log2 domain
        float rm0 = -INFINITY, rm1 = -INFINITY;
        #pragma unroll
        for (int nf = 0; nf < 4; nf++) {
            rm0 = fmaxf(rm0, fmaxf(sc[nf][0], sc[nf][1]));
            rm1 = fmaxf(rm1, fmaxf(sc[nf][2], sc[nf][3]));
        }
        rm0 = fmaxf(rm0, __shfl_xor_sync(0xffffffffu, rm0, 1));
        rm0 = fmaxf(rm0, __shfl_xor_sync(0xffffffffu, rm0, 2));
        rm1 = fmaxf(rm1, __shfl_xor_sync(0xffffffffu, rm1, 1));
        rm1 = fmaxf(rm1, __shfl_xor_sync(0xffffffffu, rm1, 2));

        const float mt0 = fmaxf(m0, rm0 * SCL);
        const float mt1 = fmaxf(m1, rm1 * SCL);
        const float c0 = exp2s(m0 - mt0);
        const float c1 = exp2s(m1 - mt1);
        m0 = mt0; m1 = mt1;

        float rs0 = 0.f, rs1 = 0.f;
        #pragma unroll
        for (int nf = 0; nf < 4; nf++) {
            const float p0 = exp2s(fmaf(sc[nf][0], SCL, -mt0));
            const float p1 = exp2s(fmaf(sc[nf][1], SCL, -mt0));
            const float p2 = exp2s(fmaf(sc[nf][2], SCL, -mt1));
            const float p3 = exp2s(fmaf(sc[nf][3], SCL, -mt1));
            rs0 += p0 + p1;
            rs1 += p2 + p3;
            const int colw = nf*8 + 2*r;
            *(uint2*)&Ps[(mrow)*PS_STRIDE + colw]     = make_uint2(f2tf32(p0), f2tf32(p1));
            *(uint2*)&Ps[(mrow + 8)*PS_STRIDE + colw] = make_uint2(f2tf32(p2), f2tf32(p3));
        }
        rs0 += __shfl_xor_sync(0xffffffffu, rs0, 1);
        rs0 += __shfl_xor_sync(0xffffffffu, rs0, 2);
        rs1 += __shfl_xor_sync(0xffffffffu, rs1, 1);
        rs1 += __shfl_xor_sync(0xffffffffu, rs1, 2);
        l0 = l0*c0 + rs0;
        l1 = l1*c1 + rs1;

        #pragma unroll
        for (int nf = 0; nf < 8; nf++) {
            oc[nf][0] *= c0; oc[nf][1] *= c0;
            oc[nf][2] *= c1; oc[nf][3] *= c1;
        }
        __syncwarp();     // P visible to own warp (P rows are warp-private)

        // O += P @ V : 4 k-steps (keys) x 8 n-frags (dh)
        #pragma unroll
        for (int ks = 0; ks < 4; ks++) {
            uint32_t af[4];
            af[0] = Ps[(mrow)*PS_STRIDE     + ks*8 + r];
            af[1] = Ps[(mrow + 8)*PS_STRIDE + ks*8 + r];
            af[2] = Ps[(mrow)*PS_STRIDE     + ks*8 + r + 4];
            af[3] = Ps[(mrow + 8)*PS_STRIDE + ks*8 + r + 4];
            #pragma unroll
            for (int nf = 0; nf < 8; nf++) {
                uint32_t bf2[2];
                bf2[0] = Vs[(ks*8 + r)*VS_STRIDE + nf*8 + qg];
                bf2[1] = Vs[(ks*8 + r + 4)*VS_STRIDE + nf*8 + qg];
                mma_tf32(oc[nf], af, bf2);
            }
        }

        __syncthreads();   // all warps done with Vs
        if (has_next) {    // V one tile ahead; hidden behind next S-MMA+softmax
            const float* vn = vg + (size_t)(kt + 1) * FA_BC * DMODEL;
            cp_async16(vs_dst, vn);
            cp_async16(vs_dst + 16, vn + 4);
            cp_async_commit();
        }
    }

    // write O (normalize by l)
    const float inv0 = 1.0f / l0;
    const float inv1 = 1.0f / l1;
    float* op  = O + base + (size_t)(q0 + mrow) * DMODEL;
    float* op8 = op + (size_t)8 * DMODEL;
    #pragma unroll
    for (int nf = 0; nf < 8; nf++) {
        const int col = nf*8 + 2*r;
        *(float2*)(op  + col) = make_float2(oc[nf][0]*inv0, oc[nf][1]*inv0);
        *(float2*)(op8 + col) = make_float2(oc[nf][2]*inv1, oc[nf][3]*inv1);
    }
}

// ------------------------------------------------------------ layernorm ----
__global__ __launch_bounds__(256) void ln_reduce(
    const float* __restrict__ a, const float* __restrict__ b,
    double* __restrict__ part)
{
    const int batch = blockIdx.y;
    const float* pa = a + (size_t)batch * NPER;
    const float* pb = b + (size_t)batch * NPER;
    float s = 0.f, ss = 0.f;
    const size_t stride4 = (size_t)gridDim.x * blockDim.x;
    for (size_t i = blockIdx.x*blockDim.x + threadIdx.x; i < NPER/4; i += stride4) {
        float4 va = *(const float4*)(pa + i*4);
        float4 vb = *(const float4*)(pb + i*4);
        float z0 = va.x + vb.x, z1 = va.y + vb.y;
        float z2 = va.z + vb.z, z3 = va.w + vb.w;
        s  += (z0 + z1) + (z2 + z3);
        ss = fmaf(z0, z0, ss); ss = fmaf(z1, z1, ss);
        ss = fmaf(z2, z2, ss); ss = fmaf(z3, z3, ss);
    }
    __shared__ double sh[512];
    int tid = threadIdx.x;
    sh[tid] = (double)s; sh[256 + tid] = (double)ss;
    __syncthreads();
    for (int st = 128; st > 0; st >>= 1) {
        if (tid < st) { sh[tid] += sh[tid+st]; sh[256+tid] += sh[256+tid+st]; }
        __syncthreads();
    }
    if (tid == 0) {
        part[(batch*256 + blockIdx.x)*2 + 0] = sh[0];
        part[(batch*256 + blockIdx.x)*2 + 1] = sh[256];
    }
}

__global__ __launch_bounds__(256) void ln_stats(
    const double* __restrict__ part, float* __restrict__ stats)
{
    const int batch = blockIdx.x;
    int tid = threadIdx.x;
    __shared__ double sh[512];
    sh[tid]       = part[(batch*256 + tid)*2 + 0];
    sh[256 + tid] = part[(batch*256 + tid)*2 + 1];
    __syncthreads();
    for (int st = 128; st > 0; st >>= 1) {
        if (tid < st) { sh[tid] += sh[tid+st]; sh[256+tid] += sh[256+tid+st]; }
        __syncthreads();
    }
    if (tid == 0) {
        double mean = sh[0] / (double)NPER;
        double var  = sh[256] / (double)NPER - mean*mean + 1e-5;
        stats[batch*2 + 0] = (float)mean;
        stats[batch*2 + 1] = (float)(1.0 / sqrt(var));
    }
}

__global__ __launch_bounds__(256) void ln_apply(
    const float* __restrict__ a, const float* __restrict__ b,
    const float* __restrict__ stats, float* __restrict__ out)
{
    const int batch = blockIdx.y;
    const float mean = stats[batch*2 + 0];
    const float inv  = stats[batch*2 + 1];
    size_t off = (size_t)batch * NPER + (size_t)(blockIdx.x*blockDim.x + threadIdx.x)*4;
    float4 va = *(const float4*)(a + off);
    float4 vb = *(const float4*)(b + off);
    float4 o;
    o.x = (va.x + vb.x - mean) * inv;
    o.y = (va.y + vb.y - mean) * inv;
    o.z = (va.z + vb.z - mean) * inv;
    o.w = (va.w + vb.w - mean) * inv;
    *(float4*)(out + off) = o;
}

// -------------------------------------------------------------- launch -----
extern "C" void kernel_launch(void* const* d_in, const int* in_sizes, int n_in,
                              void* d_out, int out_size)
{
    const float* x  = (const float*)d_in[0];
    const float* wq = (const float*)d_in[1];
    const float* bq = (const float*)d_in[2];
    const float* wk = (const float*)d_in[3];
    const float* bk = (const float*)d_in[4];
    const float* wv = (const float*)d_in[5];
    const float* bv = (const float*)d_in[6];
    const float* w1 = (const float*)d_in[7];
    const float* b1 = (const float*)d_in[8];
    const float* w2 = (const float*)d_in[9];
    const float* b2 = (const float*)d_in[10];
    float* out = (float*)d_out;

    float *q, *k, *v, *attn, *h, *ff1, *ff2, *stats;
    double* part;
    cudaGetSymbolAddress((void**)&q,    g_q);
    cudaGetSymbolAddress((void**)&k,    g_k);
    cudaGetSymbolAddress((void**)&v,    g_v);
    cudaGetSymbolAddress((void**)&attn, g_attn);
    cudaGetSymbolAddress((void**)&h,    g_h);
    cudaGetSymbolAddress((void**)&ff1,  g_ff1);
    cudaGetSymbolAddress((void**)&ff2,  g_ff2);
    cudaGetSymbolAddress((void**)&part, g_part);
    cudaGetSymbolAddress((void**)&stats, g_stats);

    // fused QKV projections (tensor cores, tf32; outputs pre-rounded)
    qkv_gemm<<<dim3(DMODEL/TBN, BL/TBM, 3), 256>>>(
        x, wq, bq, q, wk, bk, k, wv, bv, v);

    // attention (tensor cores + software exp2 + cp.async pipeline)
    flash_attn_tc<<<dim3(SEQLEN/FA_BR, NHEADS, BATCH), 256>>>(q, k, v, attn);

    // residual + LN1 -> h
    ln_reduce<<<dim3(256, BATCH), 256>>>(x, attn, part);
    ln_stats <<<BATCH, 256>>>(part, stats);
    ln_apply <<<dim3(NPER/1024, BATCH), 256>>>(x, attn, stats, h);

    // FFN (tensor cores, tf32)
    tf32_gemm_bias<<<dim3(FFDIM/TBN,  BL/TBM), 256>>>(h,   w1, b1, ff1, BL, FFDIM,  DMODEL, 1);
    tf32_gemm_bias<<<dim3(DMODEL/TBN, BL/TBM), 256>>>(ff1, w2, b2, ff2, BL, DMODEL, FFDIM,  0);

    // residual + LN2 -> out
    ln_reduce<<<dim3(256, BATCH), 256>>>(h, ff2, part);
    ln_stats <<<BATCH, 256>>>(part, stats);
    ln_apply <<<dim3(NPER/1024, BATCH), 256>>>(h, ff2, stats, out);
}

// round 14
// speedup vs baseline: 1.2573x; 1.0006x over previous
#include <cuda_runtime.h>
#include <cstdint>
#include <math.h>

#define BATCH   2
#define SEQLEN  2048
#define DMODEL  1024
#define NHEADS  16
#define DHEAD   64
#define FFDIM   4096
#define BL      (BATCH*SEQLEN)          // 4096
#define NPER    (SEQLEN*DMODEL)        // per-batch layernorm size

// ---------------- scratch (static device globals; no allocation allowed) ----
__device__ float g_q   [BL*DMODEL];
__device__ float g_k   [BL*DMODEL];
__device__ float g_v   [BL*DMODEL];
__device__ float g_attn[BL*DMODEL];
__device__ float g_h   [BL*DMODEL];
__device__ float g_ff1 [BL*FFDIM];
__device__ float g_ff2 [BL*DMODEL];
__device__ double g_part[BATCH*256*2];
__device__ float  g_stats[BATCH*2];

// --------------------------------------------------------- tf32 helpers ----
__device__ __forceinline__ uint32_t f2tf32(float x) {
    uint32_t u;
    asm("cvt.rna.tf32.f32 %0, %1;" : "=r"(u) : "f"(x));
    return u;
}

__device__ __forceinline__ void mma_tf32(float* c, const uint32_t* a, const uint32_t* b) {
    asm volatile(
        "mma.sync.aligned.m16n8k8.row.col.f32.tf32.tf32.f32 "
        "{%0,%1,%2,%3}, {%4,%5,%6,%7}, {%8,%9}, {%0,%1,%2,%3};"
        : "+f"(c[0]), "+f"(c[1]), "+f"(c[2]), "+f"(c[3])
        : "r"(a[0]), "r"(a[1]), "r"(a[2]), "r"(a[3]), "r"(b[0]), "r"(b[1]));
}

__device__ __forceinline__ void cp_async16(uint32_t saddr, const void* gptr) {
    asm volatile("cp.async.ca.shared.global [%0], [%1], 16;" :: "r"(saddr), "l"(gptr));
}
__device__ __forceinline__ void cp_async_commit() {
    asm volatile("cp.async.commit_group;");
}
__device__ __forceinline__ void cp_async_wait0() {
    asm volatile("cp.async.wait_group 0;");
}

// software 2^t on FMA/ALU pipes (avoids MUFU bottleneck). t <= 0 expected.
__device__ __forceinline__ float exp2s(float t) {
    t = fmaxf(t, -126.0f);
    float z = t + 12582912.0f;                    // round-to-int magic (1.5*2^23)
    int ni = __float_as_int(z) - 0x4B400000;
    float f = t - (z - 12582912.0f);              // f in [-0.5, 0.5]
    float p = 1.3333558e-3f;
    p = fmaf(p, f, 9.6181291e-3f);
    p = fmaf(p, f, 5.5504109e-2f);
    p = fmaf(p, f, 2.4022651e-1f);
    p = fmaf(p, f, 6.9314718e-1f);
    p = fmaf(p, f, 1.0f);
    return p * __int_as_float((ni + 127) << 23);
}

// ------------------------------------------------------------- tf32 GEMM ----
// C[M,N] = A[M,K] @ W[K,N] + bias (+relu) (+tf32-round on store).
#define TBM 128
#define TBN 128
#define TBK 16
#define ASTRIDE 20     // A smem [m][k] stride: (20*q + r) mod 32 covers all banks
#define WSTRIDE 136    // W smem [k][n] stride: bank = 8r + q, conflict-free

__device__ __forceinline__ void gemm_body(
    const float* __restrict__ A, const float* __restrict__ W,
    const float* __restrict__ bias, float* __restrict__ C,
    int M, int N, int K, int relu, int rnd, int bx, int by,
    uint32_t* As /*[2][TBM*ASTRIDE]*/, uint32_t* Ws /*[2][TBK*WSTRIDE]*/)
{
    const int tid  = threadIdx.x;
    const int lane = tid & 31;
    const int warp = tid >> 5;
    const int q = lane >> 2, r = lane & 3;
    const int wr = warp >> 2, wc = warp & 3;
    const int bm = by * TBM, bn = bx * TBN;

    const int arow = tid >> 2;
    const int akc  = (tid & 3) * 4;
    const int wrow = tid >> 5;
    const int wcol = (tid & 31) * 4;

    const float* Ag = A + (size_t)(bm + arow) * K + akc;
    const float* Wg = W + (size_t)wrow * N + bn + wcol;

    float acc[4][4][4];
    #pragma unroll
    for (int i = 0; i < 4; i++)
        #pragma unroll
        for (int j = 0; j < 4; j++)
            #pragma unroll
            for (int e = 0; e < 4; e++) acc[i][j][e] = 0.f;

    float4 ra0, ra1, rw0, rw1;

    ra0 = *(const float4*)Ag;
    ra1 = *(const float4*)(Ag + (size_t)64 * K);
    rw0 = *(const float4*)Wg;
    rw1 = *(const float4*)(Wg + (size_t)8 * N);
    Ag += TBK;
    Wg += (size_t)TBK * N;
    {
        uint4 pa0 = make_uint4(f2tf32(ra0.x), f2tf32(ra0.y), f2tf32(ra0.z), f2tf32(ra0.w));
        uint4 pa1 = make_uint4(f2tf32(ra1.x), f2tf32(ra1.y), f2tf32(ra1.z), f2tf32(ra1.w));
        uint4 pw0 = make_uint4(f2tf32(rw0.x), f2tf32(rw0.y), f2tf32(rw0.z), f2tf32(rw0.w));
        uint4 pw1 = make_uint4(f2tf32(rw1.x), f2tf32(rw1.y), f2tf32(rw1.z), f2tf32(rw1.w));
        *(uint4*)&As[arow*ASTRIDE + akc]        = pa0;
        *(uint4*)&As[(arow + 64)*ASTRIDE + akc] = pa1;
        *(uint4*)&Ws[wrow*WSTRIDE + wcol]       = pw0;
        *(uint4*)&Ws[(wrow + 8)*WSTRIDE + wcol] = pw1;
    }
    __syncthreads();

    const int nchunk = K / TBK;
    #pragma unroll 1
    for (int c = 0; c < nchunk; c++) {
        const int cur = c & 1;
        const bool has_next = (c + 1 < nchunk);
        const uint32_t* Ab = As + cur * (TBM*ASTRIDE);
        const uint32_t* Wb = Ws + cur * (TBK*WSTRIDE);

        if (has_next) {
            ra0 = *(const float4*)Ag;
            ra1 = *(const float4*)(Ag + (size_t)64 * K);
            rw0 = *(const float4*)Wg;
            rw1 = *(const float4*)(Wg + (size_t)8 * N);
            Ag += TBK;
            Wg += (size_t)TBK * N;
        }

        #pragma unroll
        for (int k8 = 0; k8 < TBK; k8 += 8) {
            uint32_t af[4][4], bf[4][2];
            #pragma unroll
            for (int tm = 0; tm < 4; tm++) {
                const int m = wr*64 + tm*16 + q;
                af[tm][0] = Ab[m*ASTRIDE + k8 + r];
                af[tm][1] = Ab[(m + 8)*ASTRIDE + k8 + r];
                af[tm][2] = Ab[m*ASTRIDE + k8 + r + 4];
                af[tm][3] = Ab[(m + 8)*ASTRIDE + k8 + r + 4];
            }
            #pragma unroll
            for (int tn = 0; tn < 4; tn++) {
                const int n = wc*32 + tn*8 + q;
                bf[tn][0] = Wb[(k8 + r)*WSTRIDE + n];
                bf[tn][1] = Wb[(k8 + r + 4)*WSTRIDE + n];
            }
            #pragma unroll
            for (int tm = 0; tm < 4; tm++)
                #pragma unroll
                for (int tn = 0; tn < 4; tn++)
                    mma_tf32(acc[tm][tn], af[tm], bf[tn]);
        }

        if (has_next) {
            uint32_t* An = As + (cur^1) * (TBM*ASTRIDE);
            uint32_t* Wn = Ws + (cur^1) * (TBK*WSTRIDE);
            uint4 pa0 = make_uint4(f2tf32(ra0.x), f2tf32(ra0.y), f2tf32(ra0.z), f2tf32(ra0.w));
            uint4 pa1 = make_uint4(f2tf32(ra1.x), f2tf32(ra1.y), f2tf32(ra1.z), f2tf32(ra1.w));
            uint4 pw0 = make_uint4(f2tf32(rw0.x), f2tf32(rw0.y), f2tf32(rw0.z), f2tf32(rw0.w));
            uint4 pw1 = make_uint4(f2tf32(rw1.x), f2tf32(rw1.y), f2tf32(rw1.z), f2tf32(rw1.w));
            *(uint4*)&An[arow*ASTRIDE + akc]        = pa0;
            *(uint4*)&An[(arow + 64)*ASTRIDE + akc] = pa1;
            *(uint4*)&Wn[wrow*WSTRIDE + wcol]       = pw0;
            *(uint4*)&Wn[(wrow + 8)*WSTRIDE + wcol] = pw1;
        }
        __syncthreads();
    }

    #pragma unroll
    for (int tm = 0; tm < 4; tm++) {
        const int row = bm + wr*64 + tm*16 + q;
        #pragma unroll
        for (int tn = 0; tn < 4; tn++) {
            const int col = bn + wc*32 + tn*8 + 2*r;
            const float2 bv = *(const float2*)(bias + col);
            float c0 = acc[tm][tn][0] + bv.x, c1 = acc[tm][tn][1] + bv.y;
            float c2 = acc[tm][tn][2] + bv.x, c3 = acc[tm][tn][3] + bv.y;
            if (relu) {
                c0 = fmaxf(c0, 0.f); c1 = fmaxf(c1, 0.f);
                c2 = fmaxf(c2, 0.f); c3 = fmaxf(c3, 0.f);
            }
            if (rnd) {   // pre-round for cp.async raw-bit consumers (idempotent)
                c0 = __uint_as_float(f2tf32(c0)); c1 = __uint_as_float(f2tf32(c1));
                c2 = __uint_as_float(f2tf32(c2)); c3 = __uint_as_float(f2tf32(c3));
            }
            *(float2*)(C + (size_t)row*N + col)       = make_float2(c0, c1);
            *(float2*)(C + (size_t)(row + 8)*N + col) = make_float2(c2, c3);
        }
    }
}

__global__ __launch_bounds__(256) void tf32_gemm_bias(
    const float* __restrict__ A, const float* __restrict__ W,
    const float* __restrict__ bias, float* __restrict__ C,
    int M, int N, int K, int relu)
{
    __shared__ uint32_t As[2*TBM*ASTRIDE];
    __shared__ uint32_t Ws[2*TBK*WSTRIDE];
    gemm_body(A, W, bias, C, M, N, K, relu, 0, blockIdx.x, blockIdx.y, As, Ws);
}

// fused QKV: blockIdx.z selects projection; outputs tf32-pre-rounded
__global__ __launch_bounds__(256) void qkv_gemm(
    const float* __restrict__ A,
    const float* __restrict__ wq, const float* __restrict__ bq, float* __restrict__ q,
    const float* __restrict__ wk, const float* __restrict__ bk, float* __restrict__ k,
    const float* __restrict__ wv, const float* __restrict__ bv, float* __restrict__ v)
{
    __shared__ uint32_t As[2*TBM*ASTRIDE];
    __shared__ uint32_t Ws[2*TBK*WSTRIDE];
    const int z = blockIdx.z;
    const float* W    = (z == 0) ? wq : (z == 1) ? wk : wv;
    const float* bias = (z == 0) ? bq : (z == 1) ? bk : bv;
    float*       C    = (z == 0) ? q  : (z == 1) ? k  : v;
    gemm_body(A, W, bias, C, BL, DMODEL, DMODEL, 0, 1, blockIdx.x, blockIdx.y, As, Ws);
}

// --------------------------------------- tensor-core flash attention -------
// cp.async pipelined: K double-buffered (issued right after S-MMA), V issued
// one tile ahead (after PV sync). K/V arrive PRE-ROUNDED to tf32 from the QKV
// epilogue, so raw-bit cp.async copies are valid tf32.
#define FA_BR 128
#define FA_BC 32
#define PS_STRIDE 36    // [qrow][key]: A-frag read bank = 4q + r, conflict-free
#define KN_STRIDE 68    // [key][dh]:   B-frag read bank = 4qg + r, conflict-free
#define VS_STRIDE 72    // [key][dh]:   B-frag read bank = 8r + qg, conflict-free

__global__ __launch_bounds__(256) void flash_attn_tc(
    const float* __restrict__ Q, const float* __restrict__ K,
    const float* __restrict__ V, float* __restrict__ O)
{
    __shared__ uint32_t Ks[2][FA_BC*KN_STRIDE];   // 17408 B
    __shared__ uint32_t Vs [FA_BC*VS_STRIDE];     //  9216 B
    __shared__ uint32_t Ps [FA_BR*PS_STRIDE];     // 18432 B

    const int tid  = threadIdx.x;
    const int lane = tid & 31;
    const int warp = tid >> 5;
    const int qg = lane >> 2, r = lane & 3;
    const int b = blockIdx.z, h = blockIdx.y;
    const int q0 = blockIdx.x * FA_BR;
    const size_t base = ((size_t)b * SEQLEN) * DMODEL + h * DHEAD;

    const int mrow = warp*16 + qg;

    // loader mapping: key = tid>>3 (0..31), col0 = (tid&7)*8 (two 16B chunks)
    const int lkey = tid >> 3;
    const int lcol = (tid & 7) * 8;
    const uint32_t ks_dst0 = (uint32_t)__cvta_generic_to_shared(&Ks[0][lkey*KN_STRIDE + lcol]);
    const uint32_t ks_dst1 = (uint32_t)__cvta_generic_to_shared(&Ks[1][lkey*KN_STRIDE + lcol]);
    const uint32_t vs_dst  = (uint32_t)__cvta_generic_to_shared(&Vs[lkey*VS_STRIDE + lcol]);
    const float* kg = K + base + (size_t)lkey * DMODEL + lcol;
    const float* vg = V + base + (size_t)lkey * DMODEL + lcol;

    // Q fragments straight from gmem (once per block)
    uint32_t qf[8][4];
    {
        const float* qp  = Q + base + (size_t)(q0 + mrow) * DMODEL;
        const float* qp8 = qp + (size_t)8 * DMODEL;
        #pragma unroll
        for (int ks = 0; ks < 8; ks++) {
            qf[ks][0] = f2tf32(__ldg(qp  + ks*8 + r));
            qf[ks][1] = f2tf32(__ldg(qp8 + ks*8 + r));
            qf[ks][2] = f2tf32(__ldg(qp  + ks*8 + r + 4));
            qf[ks][3] = f2tf32(__ldg(qp8 + ks*8 + r + 4));
        }
    }

    float oc[8][4];
    #pragma unroll
    for (int nf = 0; nf < 8; nf++)
        #pragma unroll
        for (int e = 0; e < 4; e++) oc[nf][e] = 0.f;
    float m0 = -INFINITY, m1 = -INFINITY, l0 = 0.f, l1 = 0.f;

    const float SCL = 0.125f * 1.44269504f;   // 1/sqrt(dh) * log2(e)

    // prologue: tile 0 K+V in flight
    cp_async16(ks_dst0, kg);
    cp_async16(ks_dst0 + 16, kg + 4);
    cp_async16(vs_dst, vg);
    cp_async16(vs_dst + 16, vg + 4);
    cp_async_commit();

    const int ntiles = SEQLEN / FA_BC;
    #pragma unroll 1
    for (int kt = 0; kt < ntiles; kt++) {
        const int cur = kt & 1;
        const bool has_next = (kt + 1 < ntiles);
        const uint32_t* Kb = Ks[cur];

        cp_async_wait0();      // K(kt) + V(kt) resident
        __syncthreads();

        // S = Q @ K^T : 8 k-steps (dh) x 4 n-frags (keys)
        float sc[4][4];
        #pragma unroll
        for (int nf = 0; nf < 4; nf++)
            #pragma unroll
            for (int e = 0; e < 4; e++) sc[nf][e] = 0.f;

        #pragma unroll
        for (int ks = 0; ks < 8; ks++) {
            uint32_t bfr[4][2];
            #pragma unroll
            for (int nf = 0; nf < 4; nf++) {
                bfr[nf][0] = Kb[(nf*8 + qg)*KN_STRIDE + ks*8 + r];
                bfr[nf][1] = Kb[(nf*8 + qg)*KN_STRIDE + ks*8 + r + 4];
            }
            #pragma unroll
            for (int nf = 0; nf < 4; nf++)
                mma_tf32(sc[nf], qf[ks], bfr[nf]);
        }

        // prefetch next K into the other buffer (disjoint from all readers)
        if (has_next) {
            const float* kn = kg + (size_t)(kt + 1) * FA_BC * DMODEL;
            const uint32_t kd = cur ? ks_dst0 : ks_dst1;
            cp_async16(kd, kn);
            cp_async16(kd + 16, kn + 4);
            cp_async_commit();
        }

        // online softmax in log2 domain
        float rm0 = -INFINITY, rm1 = -INFINITY;
        #pragma unroll
        for (int nf = 0; nf < 4; nf++) {
            rm0 = fmaxf(rm0, fmaxf(sc[nf][0], sc[nf][1]));
            rm1 = fmaxf(rm1, fmaxf(sc[nf][2], sc[nf][3]));
        }
        rm0 = fmaxf(rm0, __shfl_xor_sync(0xffffffffu, rm0, 1));
        rm0 = fmaxf(rm0, __shfl_xor_sync(0xffffffffu, rm0, 2));
        rm1 = fmaxf(rm1, __shfl_xor_sync(0xffffffffu, rm1, 1));
        rm1 = fmaxf(rm1, __shfl_xor_sync(0xffffffffu, rm1, 2));

        const float mt0 = fmaxf(m0, rm0 * SCL);
        const float mt1 = fmaxf(m1, rm1 * SCL);
        const float c0 = exp2s(m0 - mt0);
        const float c1 = exp2s(m1 - mt1);
        m0 = mt0; m1 = mt1;

        float rs0 = 0.f, rs1 = 0.f;
        #pragma unroll
        for (int nf = 0; nf < 4; nf++) {
            const float p0 = exp2s(fmaf(sc[nf][0], SCL, -mt0));
            const float p1 = exp2s(fmaf(sc[nf][1], SCL, -mt0));
            const float p2 = exp2s(fmaf(sc[nf][2], SCL, -mt1));
            const float p3 = exp2s(fmaf(sc[nf][3], SCL, -mt1));
            rs0 += p0 + p1;
            rs1 += p2 + p3;
            const int colw = nf*8 + 2*r;
            *(uint2*)&Ps[(mrow)*PS_STRIDE + colw]     = make_uint2(f2tf32(p0), f2tf32(p1));
            *(uint2*)&Ps[(mrow + 8)*PS_STRIDE + colw] = make_uint2(f2tf32(p2), f2tf32(p3));
        }
        rs0 += __shfl_xor_sync(0xffffffffu, rs0, 1);
        rs0 += __shfl_xor_sync(0xffffffffu, rs0, 2);
        rs1 += __shfl_xor_sync(0xffffffffu, rs1, 1);
        rs1 += __shfl_xor_sync(0xffffffffu, rs1, 2);
        l0 = l0*c0 + rs0;
        l1 = l1*c1 + rs1;

        #pragma unroll
        for (int nf = 0; nf < 8; nf++) {
            oc[nf][0] *= c0; oc[nf][1] *= c0;
            oc[nf][2] *= c1; oc[nf][3] *= c1;
        }
        __syncwarp();     // P visible to own warp (P rows are warp-private)

        // O += P @ V : 4 k-steps (keys) x 8 n-frags (dh)
        #pragma unroll
        for (int ks = 0; ks < 4; ks++) {
            uint32_t af[4];
            af[0] = Ps[(mrow)*PS_STRIDE     + ks*8 + r];
            af[1] = Ps[(mrow + 8)*PS_STRIDE + ks*8 + r];
            af[2] = Ps[(mrow)*PS_STRIDE     + ks*8 + r + 4];
            af[3] = Ps[(mrow + 8)*PS_STRIDE + ks*8 + r + 4];
            #pragma unroll
            for (int nf = 0; nf < 8; nf++) {
                uint32_t bf2[2];
                bf2[0] = Vs[(ks*8 + r)*VS_STRIDE + nf*8 + qg];
                bf2[1] = Vs[(ks*8 + r + 4)*VS_STRIDE + nf*8 + qg];
                mma_tf32(oc[nf], af, bf2);
            }
        }

        __syncthreads();   // all warps done with Vs
        if (has_next) {    // V one tile ahead; hidden behind next S-MMA+softmax
            const float* vn = vg + (size_t)(kt + 1) * FA_BC * DMODEL;
            cp_async16(vs_dst, vn);
            cp_async16(vs_dst + 16, vn + 4);
            cp_async_commit();
        }
    }

    // write O (normalize by l)
    const float inv0 = 1.0f / l0;
    const float inv1 = 1.0f / l1;
    float* op  = O + base + (size_t)(q0 + mrow) * DMODEL;
    float* op8 = op + (size_t)8 * DMODEL;
    #pragma unroll
    for (int nf = 0; nf < 8; nf++) {
        const int col = nf*8 + 2*r;
        *(float2*)(op  + col) = make_float2(oc[nf][0]*inv0, oc[nf][1]*inv0);
        *(float2*)(op8 + col) = make_float2(oc[nf][2]*inv1, oc[nf][3]*inv1);
    }
}

// ------------------------------------------------------------ layernorm ----
__global__ __launch_bounds__(256) void ln_reduce(
    const float* __restrict__ a, const float* __restrict__ b,
    double* __restrict__ part)
{
    const int batch = blockIdx.y;
    const float* pa = a + (size_t)batch * NPER;
    const float* pb = b + (size_t)batch * NPER;
    float s = 0.f, ss = 0.f;
    const size_t stride4 = (size_t)gridDim.x * blockDim.x;
    for (size_t i = blockIdx.x*blockDim.x + threadIdx.x; i < NPER/4; i += stride4) {
        float4 va = *(const float4*)(pa + i*4);
        float4 vb = *(const float4*)(pb + i*4);
        float z0 = va.x + vb.x, z1 = va.y + vb.y;
        float z2 = va.z + vb.z, z3 = va.w + vb.w;
        s  += (z0 + z1) + (z2 + z3);
        ss = fmaf(z0, z0, ss); ss = fmaf(z1, z1, ss);
        ss = fmaf(z2, z2, ss); ss = fmaf(z3, z3, ss);
    }
    __shared__ double sh[512];
    int tid = threadIdx.x;
    sh[tid] = (double)s; sh[256 + tid] = (double)ss;
    __syncthreads();
    for (int st = 128; st > 0; st >>= 1) {
        if (tid < st) { sh[tid] += sh[tid+st]; sh[256+tid] += sh[256+tid+st]; }
        __syncthreads();
    }
    if (tid == 0) {
        part[(batch*256 + blockIdx.x)*2 + 0] = sh[0];
        part[(batch*256 + blockIdx.x)*2 + 1] = sh[256];
    }
}

__global__ __launch_bounds__(256) void ln_stats(
    const double* __restrict__ part, float* __restrict__ stats)
{
    const int batch = blockIdx.x;
    int tid = threadIdx.x;
    __shared__ double sh[512];
    sh[tid]       = part[(batch*256 + tid)*2 + 0];
    sh[256 + tid] = part[(batch*256 + tid)*2 + 1];
    __syncthreads();
    for (int st = 128; st > 0; st >>= 1) {
        if (tid < st) { sh[tid] += sh[tid+st]; sh[256+tid] += sh[256+tid+st]; }
        __syncthreads();
    }
    if (tid == 0) {
        double mean = sh[0] / (double)NPER;
        double var  = sh[256] / (double)NPER - mean*mean + 1e-5;
        stats[batch*2 + 0] = (float)mean;
        stats[batch*2 + 1] = (float)(1.0 / sqrt(var));
    }
}

__global__ __launch_bounds__(256) void ln_apply(
    const float* __restrict__ a, const float* __restrict__ b,
    const float* __restrict__ stats, float* __restrict__ out)
{
    const int batch = blockIdx.y;
    const float mean = stats[batch*2 + 0];
    const float inv  = stats[batch*2 + 1];
    size_t off = (size_t)batch * NPER + (size_t)(blockIdx.x*blockDim.x + threadIdx.x)*4;
    float4 va = *(const float4*)(a + off);
    float4 vb = *(const float4*)(b + off);
    float4 o;
    o.x = (va.x + vb.x - mean) * inv;
    o.y = (va.y + vb.y - mean) * inv;
    o.z = (va.z + vb.z - mean) * inv;
    o.w = (va.w + vb.w - mean) * inv;
    *(float4*)(out + off) = o;
}

// -------------------------------------------------------------- launch -----
extern "C" void kernel_launch(void* const* d_in, const int* in_sizes, int n_in,
                              void* d_out, int out_size)
{
    const float* x  = (const float*)d_in[0];
    const float* wq = (const float*)d_in[1];
    const float* bq = (const float*)d_in[2];
    const float* wk = (const float*)d_in[3];
    const float* bk = (const float*)d_in[4];
    const float* wv = (const float*)d_in[5];
    const float* bv = (const float*)d_in[6];
    const float* w1 = (const float*)d_in[7];
    const float* b1 = (const float*)d_in[8];
    const float* w2 = (const float*)d_in[9];
    const float* b2 = (const float*)d_in[10];
    float* out = (float*)d_out;

    float *q, *k, *v, *attn, *h, *ff1, *ff2, *stats;
    double* part;
    cudaGetSymbolAddress((void**)&q,    g_q);
    cudaGetSymbolAddress((void**)&k,    g_k);
    cudaGetSymbolAddress((void**)&v,    g_v);
    cudaGetSymbolAddress((void**)&attn, g_attn);
    cudaGetSymbolAddress((void**)&h,    g_h);
    cudaGetSymbolAddress((void**)&ff1,  g_ff1);
    cudaGetSymbolAddress((void**)&ff2,  g_ff2);
    cudaGetSymbolAddress((void**)&part, g_part);
    cudaGetSymbolAddress((void**)&stats, g_stats);

    // fused QKV projections (tensor cores, tf32; outputs pre-rounded)
    qkv_gemm<<<dim3(DMODEL/TBN, BL/TBM, 3), 256>>>(
        x, wq, bq, q, wk, bk, k, wv, bv, v);

    // attention (tensor cores + software exp2 + cp.async pipeline)
    flash_attn_tc<<<dim3(SEQLEN/FA_BR, NHEADS, BATCH), 256>>>(q, k, v, attn);

    // residual + LN1 -> h
    ln_reduce<<<dim3(256, BATCH), 256>>>(x, attn, part);
    ln_stats <<<BATCH, 256>>>(part, stats);
    ln_apply <<<dim3(NPER/1024, BATCH), 256>>>(x, attn, stats, h);

    // FFN (tensor cores, tf32)
    tf32_gemm_bias<<<dim3(FFDIM/TBN,  BL/TBM), 256>>>(h,   w1, b1, ff1, BL, FFDIM,  DMODEL, 1);
    tf32_gemm_bias<<<dim3(DMODEL/TBN, BL/TBM), 256>>>(ff1, w2, b2, ff2, BL, DMODEL, FFDIM,  0);

    // residual + LN2 -> out
    ln_reduce<<<dim3(256, BATCH), 256>>>(h, ff2, part);
    ln_stats <<<BATCH, 256>>>(part, stats);
    ln_apply <<<dim3(NPER/1024, BATCH), 256>>>(h, ff2, stats, out);
}